// round 14
// baseline (speedup 1.0000x reference)
#include <cuda_runtime.h>
#include <cuda_bf16.h>
#include <stdint.h>

#define BATCH 8
#define SEQ 1024
#define HID 1024
#define NHEADS 16
#define DK 64

#define XN 8388608   // 8192*1024
#define WN 1048576   // 1024*1024

// ---------------- scratch (static __device__ — no allocs allowed) -------------
__device__ __align__(16) __nv_bfloat16 g_xh[3 * XN];
__device__ __align__(16) __nv_bfloat16 g_xl[3 * XN];
__device__ __align__(16) __nv_bfloat16 g_wh[3 * WN];
__device__ __align__(16) __nv_bfloat16 g_wl[3 * WN];
__device__ __align__(16) __nv_bfloat16 g_yh[3 * XN];
__device__ __align__(16) __nv_bfloat16 g_yl[3 * XN];
__device__ __align__(16) float g_zp[128 * 1024 * 8];
__device__ __align__(16) __nv_bfloat16 g_vph[128 * 65536];  // V' = V/Z, [bh][j][64] hi
__device__ __align__(16) __nv_bfloat16 g_vpl[128 * 65536];  // lo

// ---------------- helpers ----------------------------------------------------
__device__ __forceinline__ uint32_t saddr_of(const void* p) {
    return (uint32_t)__cvta_generic_to_shared(p);
}
__device__ __forceinline__ void cpa16(uint32_t dst, const void* src) {
    asm volatile("cp.async.cg.shared.global [%0], [%1], 16;" :: "r"(dst), "l"(src));
}
__device__ __forceinline__ void cpa_commit() {
    asm volatile("cp.async.commit_group;");
}
template <int N>
__device__ __forceinline__ void cpa_wait() {
    asm volatile("cp.async.wait_group %0;" :: "n"(N));
}
__device__ __forceinline__ void ldsm4(uint32_t r[4], uint32_t a) {
    asm volatile("ldmatrix.sync.aligned.m8n8.x4.shared.b16 {%0,%1,%2,%3}, [%4];"
                 : "=r"(r[0]), "=r"(r[1]), "=r"(r[2]), "=r"(r[3]) : "r"(a));
}
__device__ __forceinline__ void ldsm4t(uint32_t r[4], uint32_t a) {
    asm volatile("ldmatrix.sync.aligned.m8n8.x4.trans.shared.b16 {%0,%1,%2,%3}, [%4];"
                 : "=r"(r[0]), "=r"(r[1]), "=r"(r[2]), "=r"(r[3]) : "r"(a));
}
__device__ __forceinline__ void mma16816(float* c, const uint32_t* a, const uint32_t* b) {
    asm volatile("mma.sync.aligned.m16n8k16.row.col.f32.bf16.bf16.f32 "
                 "{%0,%1,%2,%3}, {%4,%5,%6,%7}, {%8,%9}, {%0,%1,%2,%3};"
                 : "+f"(c[0]), "+f"(c[1]), "+f"(c[2]), "+f"(c[3])
                 : "r"(a[0]), "r"(a[1]), "r"(a[2]), "r"(a[3]), "r"(b[0]), "r"(b[1]));
}
__device__ __forceinline__ void split2(float x, __nv_bfloat16& h, __nv_bfloat16& l) {
    h = __float2bfloat16(x);
    l = __float2bfloat16(x - __bfloat162float(h));
}
__device__ __forceinline__ void packsplit(float a, float b, uint32_t& hh, uint32_t& ll) {
    __nv_bfloat16 h0, l0, h1, l1;
    split2(a, h0, l0);
    split2(b, h1, l1);
    __nv_bfloat162 H = __halves2bfloat162(h0, h1), L = __halves2bfloat162(l0, l1);
    hh = *(uint32_t*)&H;
    ll = *(uint32_t*)&L;
}

// =============================================================================
// K0: elementwise fp32 -> split bf16 hi/lo; grid.y selects one of 3 inputs.
// =============================================================================
__global__ void __launch_bounds__(256)
split3_kernel(const float* __restrict__ X0, const float* __restrict__ X1,
              const float* __restrict__ X2, __nv_bfloat16* __restrict__ H,
              __nv_bfloat16* __restrict__ L, size_t span)
{
    const float* X = (blockIdx.y == 0) ? X0 : (blockIdx.y == 1) ? X1 : X2;
    size_t base = (size_t)blockIdx.y * span;
    size_t i = ((size_t)blockIdx.x * 256 + threadIdx.x) * 4;
    float4 v = *(const float4*)(X + i);
    __nv_bfloat16 h[4], l[4];
    split2(v.x, h[0], l[0]); split2(v.y, h[1], l[1]);
    split2(v.z, h[2], l[2]); split2(v.w, h[3], l[3]);
    *(__nv_bfloat162*)(H + base + i)     = __halves2bfloat162(h[0], h[1]);
    *(__nv_bfloat162*)(H + base + i + 2) = __halves2bfloat162(h[2], h[3]);
    *(__nv_bfloat162*)(L + base + i)     = __halves2bfloat162(l[0], l[1]);
    *(__nv_bfloat162*)(L + base + i + 2) = __halves2bfloat162(l[2], l[3]);
}

// =============================================================================
// K1: projection  Y[m,n] = sum_k X[m,k] * W[n,k]  (z = q/k/v)
//     cp.async 2-stage pipeline, 80KB dyn smem.
// =============================================================================
__global__ void __launch_bounds__(256)
proj_mma(const __nv_bfloat16* __restrict__ Xh, const __nv_bfloat16* __restrict__ Xl,
         const __nv_bfloat16* __restrict__ Wh, const __nv_bfloat16* __restrict__ Wl,
         __nv_bfloat16* __restrict__ Yh, __nv_bfloat16* __restrict__ Yl)
{
    extern __shared__ __align__(16) __nv_bfloat16 smem[];

    const int tid = threadIdx.x, lane = tid & 31, w = tid >> 5;
    const int wm = w >> 2, wn = w & 3;
    const int z = blockIdx.z;
    const size_t xoff = (size_t)z * XN, woff = (size_t)z * WN;
    Xh += xoff; Xl += xoff; Yh += xoff; Yl += xoff; Wh += woff; Wl += woff;
    const int m0 = blockIdx.y * 128, n0 = blockIdx.x * 128;

    const int lr = tid >> 2, lc = (tid & 3) * 8;

    float acc[4][4][4] = {};

#define STG(s, off) (smem + (s) * 20480 + (off))
    auto load_stage = [&](int s, int k0) {
#pragma unroll
        for (int q = 0; q < 2; q++) {
            int r = lr + q * 64;
            cpa16(saddr_of(STG(s, 0)     + r * 40 + lc), Xh + (size_t)(m0 + r) * 1024 + k0 + lc);
            cpa16(saddr_of(STG(s, 5120)  + r * 40 + lc), Xl + (size_t)(m0 + r) * 1024 + k0 + lc);
            cpa16(saddr_of(STG(s, 10240) + r * 40 + lc), Wh + (size_t)(n0 + r) * 1024 + k0 + lc);
            cpa16(saddr_of(STG(s, 15360) + r * 40 + lc), Wl + (size_t)(n0 + r) * 1024 + k0 + lc);
        }
    };

    load_stage(0, 0);
    cpa_commit();

    for (int it = 0; it < 32; it++) {
        const int cur = it & 1;
        if (it + 1 < 32) {
            load_stage(cur ^ 1, (it + 1) * 32);
            cpa_commit();
            cpa_wait<1>();
        } else {
            cpa_wait<0>();
        }
        __syncthreads();

        const __nv_bfloat16* Ah = STG(cur, 0);
        const __nv_bfloat16* Al = STG(cur, 5120);
        const __nv_bfloat16* Bh = STG(cur, 10240);
        const __nv_bfloat16* Bl = STG(cur, 15360);

#pragma unroll
        for (int ks = 0; ks < 32; ks += 16) {
            uint32_t ah[4][4], al[4][4], bh[4][2], bl[4][2];
#pragma unroll
            for (int mt = 0; mt < 4; mt++) {
                int row = wm * 64 + mt * 16 + (lane & 15);
                int col = ks + ((lane >> 4) << 3);
                ldsm4(ah[mt], saddr_of(Ah + row * 40 + col));
                ldsm4(al[mt], saddr_of(Al + row * 40 + col));
            }
#pragma unroll
            for (int p = 0; p < 2; p++) {
                int row = wn * 32 + p * 16 + ((lane >> 4) << 3) + (lane & 7);
                int col = ks + (((lane >> 3) & 1) << 3);
                uint32_t t4[4];
                ldsm4(t4, saddr_of(Bh + row * 40 + col));
                bh[p * 2][0] = t4[0]; bh[p * 2][1] = t4[1];
                bh[p * 2 + 1][0] = t4[2]; bh[p * 2 + 1][1] = t4[3];
                ldsm4(t4, saddr_of(Bl + row * 40 + col));
                bl[p * 2][0] = t4[0]; bl[p * 2][1] = t4[1];
                bl[p * 2 + 1][0] = t4[2]; bl[p * 2 + 1][1] = t4[3];
            }
#pragma unroll
            for (int mt = 0; mt < 4; mt++)
#pragma unroll
                for (int nt = 0; nt < 4; nt++) {
                    mma16816(acc[mt][nt], ah[mt], bh[nt]);
                    mma16816(acc[mt][nt], ah[mt], bl[nt]);
                    mma16816(acc[mt][nt], al[mt], bh[nt]);
                }
        }
        __syncthreads();
    }
#undef STG

    const int gr = lane >> 2, gc = (lane & 3) << 1;
#pragma unroll
    for (int mt = 0; mt < 4; mt++)
#pragma unroll
        for (int nt = 0; nt < 4; nt++) {
            int m = m0 + wm * 64 + mt * 16 + gr;
            int n = n0 + wn * 32 + nt * 8 + gc;
#pragma unroll
            for (int hf = 0; hf < 2; hf++) {
                float c0 = acc[mt][nt][hf * 2], c1 = acc[mt][nt][hf * 2 + 1];
                __nv_bfloat16 h0, l0, h1, l1;
                split2(c0, h0, l0);
                split2(c1, h1, l1);
                size_t off = (size_t)(m + hf * 8) * 1024 + n;
                *(__nv_bfloat162*)(Yh + off) = __halves2bfloat162(h0, h1);
                *(__nv_bfloat162*)(Yl + off) = __halves2bfloat162(l0, l1);
            }
        }
}

// =============================================================================
// K2: zscore — S = QK^T, exp, deterministic row-sum partials ONLY (no E write).
// =============================================================================
__global__ void __launch_bounds__(256)
zscore_mma(const __nv_bfloat16* __restrict__ Qh, const __nv_bfloat16* __restrict__ Ql,
           const __nv_bfloat16* __restrict__ Kh, const __nv_bfloat16* __restrict__ Kl,
           float* __restrict__ Zp)
{
    extern __shared__ __align__(16) __nv_bfloat16 smem[];
    __nv_bfloat16* Ah = smem;            // [128][72]
    __nv_bfloat16* Al = smem + 9216;
    __nv_bfloat16* Bh = smem + 18432;
    __nv_bfloat16* Bl = smem + 27648;
    __shared__ __align__(16) float srow[128][4];

    const int tid = threadIdx.x, lane = tid & 31, w = tid >> 5;
    const int wm = w >> 2, wn = w & 3;
    const int bhz = blockIdx.z, b = bhz >> 4, h = bhz & 15;
    const int m0 = blockIdx.y * 128, n0 = blockIdx.x * 128;

    const size_t qbase = (size_t)(b * 1024 + m0) * 1024 + h * 64;
    const size_t kbase = (size_t)(b * 1024 + n0) * 1024 + h * 64;

#pragma unroll
    for (int it = 0; it < 4; it++) {
        int id = tid + it * 256;
        int r = id >> 3, c = (id & 7) * 8;
        cpa16(saddr_of(Ah + r * 72 + c), Qh + qbase + (size_t)r * 1024 + c);
        cpa16(saddr_of(Al + r * 72 + c), Ql + qbase + (size_t)r * 1024 + c);
        cpa16(saddr_of(Bh + r * 72 + c), Kh + kbase + (size_t)r * 1024 + c);
        cpa16(saddr_of(Bl + r * 72 + c), Kl + kbase + (size_t)r * 1024 + c);
    }
    cpa_commit();
    cpa_wait<0>();
    __syncthreads();

    float acc[4][4][4] = {};
#pragma unroll
    for (int ks = 0; ks < 64; ks += 16) {
        uint32_t ah[4][4], al[4][4], bh[4][2], bl[4][2];
#pragma unroll
        for (int mt = 0; mt < 4; mt++) {
            int row = wm * 64 + mt * 16 + (lane & 15);
            int col = ks + ((lane >> 4) << 3);
            ldsm4(ah[mt], saddr_of(Ah + row * 72 + col));
            ldsm4(al[mt], saddr_of(Al + row * 72 + col));
        }
#pragma unroll
        for (int p = 0; p < 2; p++) {
            int row = wn * 32 + p * 16 + ((lane >> 4) << 3) + (lane & 7);
            int col = ks + (((lane >> 3) & 1) << 3);
            uint32_t t4[4];
            ldsm4(t4, saddr_of(Bh + row * 72 + col));
            bh[p * 2][0] = t4[0]; bh[p * 2][1] = t4[1];
            bh[p * 2 + 1][0] = t4[2]; bh[p * 2 + 1][1] = t4[3];
            ldsm4(t4, saddr_of(Bl + row * 72 + col));
            bl[p * 2][0] = t4[0]; bl[p * 2][1] = t4[1];
            bl[p * 2 + 1][0] = t4[2]; bl[p * 2 + 1][1] = t4[3];
        }
#pragma unroll
        for (int mt = 0; mt < 4; mt++)
#pragma unroll
            for (int nt = 0; nt < 4; nt++) {
                mma16816(acc[mt][nt], ah[mt], bh[nt]);
                mma16816(acc[mt][nt], ah[mt], bl[nt]);
                mma16816(acc[mt][nt], al[mt], bh[nt]);
            }
    }

#pragma unroll
    for (int mt = 0; mt < 4; mt++)
#pragma unroll
        for (int nt = 0; nt < 4; nt++)
#pragma unroll
            for (int q = 0; q < 4; q++)
                acc[mt][nt][q] = __expf(acc[mt][nt][q] * 0.125f);

    const int gr = lane >> 2;

#pragma unroll
    for (int mt = 0; mt < 4; mt++) {
        float s_lo = 0.f, s_hi = 0.f;
#pragma unroll
        for (int nt = 0; nt < 4; nt++) {
            s_lo += acc[mt][nt][0] + acc[mt][nt][1];
            s_hi += acc[mt][nt][2] + acc[mt][nt][3];
        }
        s_lo += __shfl_xor_sync(0xffffffffu, s_lo, 1);
        s_lo += __shfl_xor_sync(0xffffffffu, s_lo, 2);
        s_hi += __shfl_xor_sync(0xffffffffu, s_hi, 1);
        s_hi += __shfl_xor_sync(0xffffffffu, s_hi, 2);
        if ((lane & 3) == 0) {
            srow[wm * 64 + mt * 16 + gr][wn]     = s_lo;
            srow[wm * 64 + mt * 16 + gr + 8][wn] = s_hi;
        }
    }
    __syncthreads();
    if (tid < 128) {
        float zp = srow[tid][0] + srow[tid][1] + srow[tid][2] + srow[tid][3];
        Zp[((size_t)(bhz << 10) + m0 + tid) * 8 + (n0 >> 7)] = zp;
    }
}

// =============================================================================
// K3: fused zred+vscale. One warp per (bh,j) row.
// =============================================================================
__global__ void __launch_bounds__(256)
zvscale_kernel(const __nv_bfloat16* __restrict__ Vh, const __nv_bfloat16* __restrict__ Vl,
               const float* __restrict__ Zp,
               __nv_bfloat16* __restrict__ Ph, __nv_bfloat16* __restrict__ Pl)
{
    int wid = blockIdx.x * 8 + (threadIdx.x >> 5);   // 0 .. 131071 (bh*1024 + j)
    int lane = threadIdx.x & 31;
    int bh = wid >> 10, j = wid & 1023;
    int b = bh >> 4, h = bh & 15;

    float zpart = (lane < 8) ? Zp[(size_t)wid * 8 + lane] : 0.f;
    zpart += __shfl_xor_sync(0xffffffffu, zpart, 4);
    zpart += __shfl_xor_sync(0xffffffffu, zpart, 2);
    zpart += __shfl_xor_sync(0xffffffffu, zpart, 1);
    float inv = 1.f / __shfl_sync(0xffffffffu, zpart, 0);

    size_t src = (size_t)(b * 1024 + j) * 1024 + h * 64 + lane * 2;
    __nv_bfloat162 vh2 = *(const __nv_bfloat162*)(Vh + src);
    __nv_bfloat162 vl2 = *(const __nv_bfloat162*)(Vl + src);
    float v0 = (__bfloat162float(__low2bfloat16(vh2)) + __bfloat162float(__low2bfloat16(vl2))) * inv;
    float v1 = (__bfloat162float(__high2bfloat16(vh2)) + __bfloat162float(__high2bfloat16(vl2))) * inv;
    __nv_bfloat16 h0, l0, h1, l1;
    split2(v0, h0, l0);
    split2(v1, h1, l1);
    size_t dst = (size_t)wid * 64 + lane * 2;
    *(__nv_bfloat162*)(Ph + dst) = __halves2bfloat162(h0, h1);
    *(__nv_bfloat162*)(Pl + dst) = __halves2bfloat162(l0, l1);
}

// =============================================================================
// K4: fused out, j-chunk = 64.  out[i,d] = sum_{j<=i} exp(s[j,i]) * V'[j,d].
//     smem: K tile 36KB + 2-stage Q 36KB + 2-stage V 36KB = 108KB.
// =============================================================================
__global__ void __launch_bounds__(256)
fused_out(const __nv_bfloat16* __restrict__ Qh, const __nv_bfloat16* __restrict__ Ql,
          const __nv_bfloat16* __restrict__ Kh, const __nv_bfloat16* __restrict__ Kl,
          const __nv_bfloat16* __restrict__ Vh, const __nv_bfloat16* __restrict__ Vl,
          float* __restrict__ Out)
{
    extern __shared__ __align__(16) __nv_bfloat16 smem[];
    // elems: Ksh 0, Ksl 9216, Q stage s at 18432+s*9216 (hi 4608 elems, lo +4608),
    //        V stage s at 36864+s*9216 (same split)
    __nv_bfloat16* Ksh = smem;
    __nv_bfloat16* Ksl = smem + 9216;

    const int tid = threadIdx.x, lane = tid & 31, w = tid >> 5;
    const int bhz = blockIdx.y, b = bhz >> 4, h = bhz & 15;
    const int i0 = (7 - (int)blockIdx.x) * 128;   // longest-first

    const size_t kbase = (size_t)(b * 1024 + i0) * 1024 + h * 64;
    const size_t qrow0 = (size_t)(b * 1024) * 1024 + h * 64;
    const size_t vrow0 = (size_t)bhz << 16;

    const int gr = lane >> 2, gc = (lane & 3) << 1;
    const int njc = (i0 >> 6) + 2;                // chunks of 64

    // ---- load K tile ----
#pragma unroll
    for (int it = 0; it < 4; it++) {
        int id = tid + it * 256;
        int r = id >> 3, c = (id & 7) * 8;
        cpa16(saddr_of(Ksh + r * 72 + c), Kh + kbase + (size_t)r * 1024 + c);
        cpa16(saddr_of(Ksl + r * 72 + c), Kl + kbase + (size_t)r * 1024 + c);
    }

    auto load_chunk = [&](int jc, int s) {
        __nv_bfloat16* Qsh = smem + 18432 + s * 9216;
        __nv_bfloat16* Qsl = Qsh + 4608;
        __nv_bfloat16* Vsh = smem + 36864 + s * 9216;
        __nv_bfloat16* Vsl = Vsh + 4608;
        int j0 = jc * 64;
        // 64 rows x 8 col-groups = 512 slots; 256 threads x 2 iters
#pragma unroll
        for (int it = 0; it < 2; it++) {
            int id = tid + it * 256;
            int r = id >> 3, c = (id & 7) * 8;
            cpa16(saddr_of(Qsh + r * 72 + c), Qh + qrow0 + (size_t)(j0 + r) * 1024 + c);
            cpa16(saddr_of(Qsl + r * 72 + c), Ql + qrow0 + (size_t)(j0 + r) * 1024 + c);
            cpa16(saddr_of(Vsh + r * 72 + c), Vh + vrow0 + (size_t)(j0 + r) * 64 + c);
            cpa16(saddr_of(Vsl + r * 72 + c), Vl + vrow0 + (size_t)(j0 + r) * 64 + c);
        }
        cpa_commit();
    };

    load_chunk(0, 0);       // K + chunk0 in one group
    cpa_wait<0>();
    __syncthreads();

    // hoist K A-fragments (16 i-rows per warp, K=64)
    uint32_t kah[4][4], kal[4][4];
#pragma unroll
    for (int kd = 0; kd < 4; kd++) {
        int row = w * 16 + (lane & 15);
        int col = kd * 16 + ((lane >> 4) << 3);
        ldsm4(kah[kd], saddr_of(Ksh + row * 72 + col));
        ldsm4(kal[kd], saddr_of(Ksl + row * 72 + col));
    }

    if (njc > 1) load_chunk(1, 1);

    float acc2[8][4] = {};
    const int ibase = i0 + w * 16 + gr;

    for (int jc = 0; jc < njc; jc++) {
        const int s = jc & 1;
        cpa_wait<0>();
        __syncthreads();
        if (jc + 1 < njc) load_chunk(jc + 1, s ^ 1);

        const __nv_bfloat16* Qsh = smem + 18432 + s * 9216;
        const __nv_bfloat16* Qsl = Qsh + 4608;
        const __nv_bfloat16* Vsh = smem + 36864 + s * 9216;
        const __nv_bfloat16* Vsl = Vsh + 4608;

        // ---- mma1: S'[16 i-rows, 64 j-cols] ----
        float acc1[8][4] = {};
#pragma unroll
        for (int kd = 0; kd < 4; kd++) {
            int ks = kd * 16;
            uint32_t qbh[8][2], qbl[8][2];
#pragma unroll
            for (int p = 0; p < 4; p++) {
                int row = p * 16 + ((lane >> 4) << 3) + (lane & 7);
                int col = ks + (((lane >> 3) & 1) << 3);
                uint32_t t4[4];
                ldsm4(t4, saddr_of(Qsh + row * 72 + col));
                qbh[p * 2][0] = t4[0]; qbh[p * 2][1] = t4[1];
                qbh[p * 2 + 1][0] = t4[2]; qbh[p * 2 + 1][1] = t4[3];
                ldsm4(t4, saddr_of(Qsl + row * 72 + col));
                qbl[p * 2][0] = t4[0]; qbl[p * 2][1] = t4[1];
                qbl[p * 2 + 1][0] = t4[2]; qbl[p * 2 + 1][1] = t4[3];
            }
#pragma unroll
            for (int nt = 0; nt < 8; nt++) {
                mma16816(acc1[nt], kah[kd], qbh[nt]);
                mma16816(acc1[nt], kah[kd], qbl[nt]);
                mma16816(acc1[nt], kal[kd], qbh[nt]);
            }
        }

        // ---- exp + mask (keep j <= i) ----
        const int j0 = jc * 64;
#pragma unroll
        for (int nt = 0; nt < 8; nt++) {
            int jg = j0 + nt * 8 + gc;
#pragma unroll
            for (int q = 0; q < 4; q++) {
                int jj = jg + (q & 1);
                int ii = ibase + ((q >> 1) << 3);
                acc1[nt][q] = (jj <= ii) ? __expf(acc1[nt][q] * 0.125f) : 0.f;
            }
        }

        // ---- C-frag -> A-frag repack (split bf16), 4 k16 groups ----
        uint32_t pah[4][4], pal[4][4];
#pragma unroll
        for (int kj = 0; kj < 4; kj++) {
            const float* x0 = acc1[2 * kj];
            const float* x1 = acc1[2 * kj + 1];
            packsplit(x0[0], x0[1], pah[kj][0], pal[kj][0]);
            packsplit(x0[2], x0[3], pah[kj][1], pal[kj][1]);
            packsplit(x1[0], x1[1], pah[kj][2], pal[kj][2]);
            packsplit(x1[2], x1[3], pah[kj][3], pal[kj][3]);
        }

        // ---- mma2: out += P' * V' ----
#pragma unroll
        for (int kj = 0; kj < 4; kj++) {
            int kr = kj * 16 + (((lane >> 3) & 1) << 3) + (lane & 7);
            uint32_t vbh[8][2], vbl[8][2];
#pragma unroll
            for (int qd = 0; qd < 4; qd++) {
                int dc = qd * 16 + ((lane >> 4) << 3);
                uint32_t t4[4];
                ldsm4t(t4, saddr_of(Vsh + kr * 72 + dc));
                vbh[qd * 2][0] = t4[0]; vbh[qd * 2][1] = t4[1];
                vbh[qd * 2 + 1][0] = t4[2]; vbh[qd * 2 + 1][1] = t4[3];
                ldsm4t(t4, saddr_of(Vsl + kr * 72 + dc));
                vbl[qd * 2][0] = t4[0]; vbl[qd * 2][1] = t4[1];
                vbl[qd * 2 + 1][0] = t4[2]; vbl[qd * 2 + 1][1] = t4[3];
            }
#pragma unroll
            for (int nt2 = 0; nt2 < 8; nt2++) {
                mma16816(acc2[nt2], pah[kj], vbh[nt2]);
                mma16816(acc2[nt2], pah[kj], vbl[nt2]);
                mma16816(acc2[nt2], pal[kj], vbh[nt2]);
            }
        }
        __syncthreads();
    }

    // ---- store out ----
#pragma unroll
    for (int nt2 = 0; nt2 < 8; nt2++) {
        int d = nt2 * 8 + gc;
#pragma unroll
        for (int hf = 0; hf < 2; hf++) {
            int i = ibase + hf * 8;
            *(float2*)(Out + (size_t)(b * 1024 + i) * 1024 + h * 64 + d) =
                make_float2(acc2[nt2][hf * 2], acc2[nt2][hf * 2 + 1]);
        }
    }
}

// =============================================================================
extern "C" void kernel_launch(void* const* d_in, const int* in_sizes, int n_in,
                              void* d_out, int out_size)
{
    const float* q  = (const float*)d_in[0];
    const float* k  = (const float*)d_in[1];
    const float* v  = (const float*)d_in[2];
    const float* Wq = (const float*)d_in[3];
    const float* Wk = (const float*)d_in[4];
    const float* Wv = (const float*)d_in[5];
    float* out = (float*)d_out;
    (void)in_sizes; (void)n_in; (void)out_size;

    __nv_bfloat16 *xh, *xl, *wh, *wl, *yh, *yl, *vph, *vpl;
    float *zp;
    cudaGetSymbolAddress((void**)&xh, g_xh);
    cudaGetSymbolAddress((void**)&xl, g_xl);
    cudaGetSymbolAddress((void**)&wh, g_wh);
    cudaGetSymbolAddress((void**)&wl, g_wl);
    cudaGetSymbolAddress((void**)&yh, g_yh);
    cudaGetSymbolAddress((void**)&yl, g_yl);
    cudaGetSymbolAddress((void**)&zp, g_zp);
    cudaGetSymbolAddress((void**)&vph, g_vph);
    cudaGetSymbolAddress((void**)&vpl, g_vpl);

    cudaFuncSetAttribute(proj_mma,   cudaFuncAttributeMaxDynamicSharedMemorySize, 81920);
    cudaFuncSetAttribute(zscore_mma, cudaFuncAttributeMaxDynamicSharedMemorySize, 73728);
    cudaFuncSetAttribute(fused_out,  cudaFuncAttributeMaxDynamicSharedMemorySize, 110592);

    split3_kernel<<<dim3(XN / 1024, 3), 256>>>(q, k, v, xh, xl, (size_t)XN);
    split3_kernel<<<dim3(WN / 1024, 3), 256>>>(Wq, Wk, Wv, wh, wl, (size_t)WN);

    proj_mma<<<dim3(8, 64, 3), 256, 81920>>>(xh, xl, wh, wl, yh, yl);

    dim3 sgrid(8, 8, BATCH * NHEADS);
    zscore_mma<<<sgrid, 256, 73728>>>(yh, yl, yh + XN, yl + XN, zp);

    zvscale_kernel<<<16384, 256>>>(yh + 2 * XN, yl + 2 * XN, zp, vph, vpl);

    fused_out<<<dim3(8, BATCH * NHEADS), 256, 110592>>>(
        yh, yl, yh + XN, yl + XN, vph, vpl, out);
}

// round 15
// speedup vs baseline: 1.0201x; 1.0201x over previous
#include <cuda_runtime.h>
#include <cuda_bf16.h>
#include <stdint.h>

#define BATCH 8
#define SEQ 1024
#define HID 1024
#define NHEADS 16
#define DK 64

#define XN 8388608   // 8192*1024
#define WN 1048576   // 1024*1024

// ---------------- scratch (static __device__ — no allocs allowed) -------------
__device__ __align__(16) __nv_bfloat16 g_xh[3 * XN];
__device__ __align__(16) __nv_bfloat16 g_xl[3 * XN];
__device__ __align__(16) __nv_bfloat16 g_wh[3 * WN];
__device__ __align__(16) __nv_bfloat16 g_wl[3 * WN];
__device__ __align__(16) __nv_bfloat16 g_yh[3 * XN];
__device__ __align__(16) __nv_bfloat16 g_yl[3 * XN];
__device__ __align__(16) float g_zp[128 * 1024 * 8];
__device__ __align__(16) __nv_bfloat16 g_vph[128 * 65536];  // V' = V/Z, [bh][j][64] hi
__device__ __align__(16) __nv_bfloat16 g_vpl[128 * 65536];  // lo

// ---------------- helpers ----------------------------------------------------
__device__ __forceinline__ uint32_t saddr_of(const void* p) {
    return (uint32_t)__cvta_generic_to_shared(p);
}
__device__ __forceinline__ void cpa16(uint32_t dst, const void* src) {
    asm volatile("cp.async.cg.shared.global [%0], [%1], 16;" :: "r"(dst), "l"(src));
}
__device__ __forceinline__ void cpa_commit() {
    asm volatile("cp.async.commit_group;");
}
template <int N>
__device__ __forceinline__ void cpa_wait() {
    asm volatile("cp.async.wait_group %0;" :: "n"(N));
}
__device__ __forceinline__ void ldsm4(uint32_t r[4], uint32_t a) {
    asm volatile("ldmatrix.sync.aligned.m8n8.x4.shared.b16 {%0,%1,%2,%3}, [%4];"
                 : "=r"(r[0]), "=r"(r[1]), "=r"(r[2]), "=r"(r[3]) : "r"(a));
}
__device__ __forceinline__ void ldsm4t(uint32_t r[4], uint32_t a) {
    asm volatile("ldmatrix.sync.aligned.m8n8.x4.trans.shared.b16 {%0,%1,%2,%3}, [%4];"
                 : "=r"(r[0]), "=r"(r[1]), "=r"(r[2]), "=r"(r[3]) : "r"(a));
}
__device__ __forceinline__ void mma16816(float* c, const uint32_t* a, const uint32_t* b) {
    asm volatile("mma.sync.aligned.m16n8k16.row.col.f32.bf16.bf16.f32 "
                 "{%0,%1,%2,%3}, {%4,%5,%6,%7}, {%8,%9}, {%0,%1,%2,%3};"
                 : "+f"(c[0]), "+f"(c[1]), "+f"(c[2]), "+f"(c[3])
                 : "r"(a[0]), "r"(a[1]), "r"(a[2]), "r"(a[3]), "r"(b[0]), "r"(b[1]));
}
__device__ __forceinline__ void split2(float x, __nv_bfloat16& h, __nv_bfloat16& l) {
    h = __float2bfloat16(x);
    l = __float2bfloat16(x - __bfloat162float(h));
}
__device__ __forceinline__ void packsplit(float a, float b, uint32_t& hh, uint32_t& ll) {
    __nv_bfloat16 h0, l0, h1, l1;
    split2(a, h0, l0);
    split2(b, h1, l1);
    __nv_bfloat162 H = __halves2bfloat162(h0, h1), L = __halves2bfloat162(l0, l1);
    hh = *(uint32_t*)&H;
    ll = *(uint32_t*)&L;
}

// =============================================================================
// K0: elementwise fp32 -> split bf16 hi/lo; grid.y selects one of 3 inputs.
// =============================================================================
__global__ void __launch_bounds__(256)
split3_kernel(const float* __restrict__ X0, const float* __restrict__ X1,
              const float* __restrict__ X2, __nv_bfloat16* __restrict__ H,
              __nv_bfloat16* __restrict__ L, size_t span)
{
    const float* X = (blockIdx.y == 0) ? X0 : (blockIdx.y == 1) ? X1 : X2;
    size_t base = (size_t)blockIdx.y * span;
    size_t i = ((size_t)blockIdx.x * 256 + threadIdx.x) * 4;
    float4 v = *(const float4*)(X + i);
    __nv_bfloat16 h[4], l[4];
    split2(v.x, h[0], l[0]); split2(v.y, h[1], l[1]);
    split2(v.z, h[2], l[2]); split2(v.w, h[3], l[3]);
    *(__nv_bfloat162*)(H + base + i)     = __halves2bfloat162(h[0], h[1]);
    *(__nv_bfloat162*)(H + base + i + 2) = __halves2bfloat162(h[2], h[3]);
    *(__nv_bfloat162*)(L + base + i)     = __halves2bfloat162(l[0], l[1]);
    *(__nv_bfloat162*)(L + base + i + 2) = __halves2bfloat162(l[2], l[3]);
}

// =============================================================================
// K1: projection  Y[m,n] = sum_k X[m,k] * W[n,k]  (z = q/k/v)
//     cp.async 2-stage pipeline, 80KB dyn smem.
// =============================================================================
__global__ void __launch_bounds__(256)
proj_mma(const __nv_bfloat16* __restrict__ Xh, const __nv_bfloat16* __restrict__ Xl,
         const __nv_bfloat16* __restrict__ Wh, const __nv_bfloat16* __restrict__ Wl,
         __nv_bfloat16* __restrict__ Yh, __nv_bfloat16* __restrict__ Yl)
{
    extern __shared__ __align__(16) __nv_bfloat16 smem[];

    const int tid = threadIdx.x, lane = tid & 31, w = tid >> 5;
    const int wm = w >> 2, wn = w & 3;
    const int z = blockIdx.z;
    const size_t xoff = (size_t)z * XN, woff = (size_t)z * WN;
    Xh += xoff; Xl += xoff; Yh += xoff; Yl += xoff; Wh += woff; Wl += woff;
    const int m0 = blockIdx.y * 128, n0 = blockIdx.x * 128;

    const int lr = tid >> 2, lc = (tid & 3) * 8;

    float acc[4][4][4] = {};

#define STG(s, off) (smem + (s) * 20480 + (off))
    auto load_stage = [&](int s, int k0) {
#pragma unroll
        for (int q = 0; q < 2; q++) {
            int r = lr + q * 64;
            cpa16(saddr_of(STG(s, 0)     + r * 40 + lc), Xh + (size_t)(m0 + r) * 1024 + k0 + lc);
            cpa16(saddr_of(STG(s, 5120)  + r * 40 + lc), Xl + (size_t)(m0 + r) * 1024 + k0 + lc);
            cpa16(saddr_of(STG(s, 10240) + r * 40 + lc), Wh + (size_t)(n0 + r) * 1024 + k0 + lc);
            cpa16(saddr_of(STG(s, 15360) + r * 40 + lc), Wl + (size_t)(n0 + r) * 1024 + k0 + lc);
        }
    };

    load_stage(0, 0);
    cpa_commit();

    for (int it = 0; it < 32; it++) {
        const int cur = it & 1;
        if (it + 1 < 32) {
            load_stage(cur ^ 1, (it + 1) * 32);
            cpa_commit();
            cpa_wait<1>();
        } else {
            cpa_wait<0>();
        }
        __syncthreads();

        const __nv_bfloat16* Ah = STG(cur, 0);
        const __nv_bfloat16* Al = STG(cur, 5120);
        const __nv_bfloat16* Bh = STG(cur, 10240);
        const __nv_bfloat16* Bl = STG(cur, 15360);

#pragma unroll
        for (int ks = 0; ks < 32; ks += 16) {
            uint32_t ah[4][4], al[4][4], bh[4][2], bl[4][2];
#pragma unroll
            for (int mt = 0; mt < 4; mt++) {
                int row = wm * 64 + mt * 16 + (lane & 15);
                int col = ks + ((lane >> 4) << 3);
                ldsm4(ah[mt], saddr_of(Ah + row * 40 + col));
                ldsm4(al[mt], saddr_of(Al + row * 40 + col));
            }
#pragma unroll
            for (int p = 0; p < 2; p++) {
                int row = wn * 32 + p * 16 + ((lane >> 4) << 3) + (lane & 7);
                int col = ks + (((lane >> 3) & 1) << 3);
                uint32_t t4[4];
                ldsm4(t4, saddr_of(Bh + row * 40 + col));
                bh[p * 2][0] = t4[0]; bh[p * 2][1] = t4[1];
                bh[p * 2 + 1][0] = t4[2]; bh[p * 2 + 1][1] = t4[3];
                ldsm4(t4, saddr_of(Bl + row * 40 + col));
                bl[p * 2][0] = t4[0]; bl[p * 2][1] = t4[1];
                bl[p * 2 + 1][0] = t4[2]; bl[p * 2 + 1][1] = t4[3];
            }
#pragma unroll
            for (int mt = 0; mt < 4; mt++)
#pragma unroll
                for (int nt = 0; nt < 4; nt++) {
                    mma16816(acc[mt][nt], ah[mt], bh[nt]);
                    mma16816(acc[mt][nt], ah[mt], bl[nt]);
                    mma16816(acc[mt][nt], al[mt], bh[nt]);
                }
        }
        __syncthreads();
    }
#undef STG

    const int gr = lane >> 2, gc = (lane & 3) << 1;
#pragma unroll
    for (int mt = 0; mt < 4; mt++)
#pragma unroll
        for (int nt = 0; nt < 4; nt++) {
            int m = m0 + wm * 64 + mt * 16 + gr;
            int n = n0 + wn * 32 + nt * 8 + gc;
#pragma unroll
            for (int hf = 0; hf < 2; hf++) {
                float c0 = acc[mt][nt][hf * 2], c1 = acc[mt][nt][hf * 2 + 1];
                __nv_bfloat16 h0, l0, h1, l1;
                split2(c0, h0, l0);
                split2(c1, h1, l1);
                size_t off = (size_t)(m + hf * 8) * 1024 + n;
                *(__nv_bfloat162*)(Yh + off) = __halves2bfloat162(h0, h1);
                *(__nv_bfloat162*)(Yl + off) = __halves2bfloat162(l0, l1);
            }
        }
}

// =============================================================================
// K2: zscore — S = QK^T, exp, deterministic row-sum partials ONLY (no E write).
// =============================================================================
__global__ void __launch_bounds__(256)
zscore_mma(const __nv_bfloat16* __restrict__ Qh, const __nv_bfloat16* __restrict__ Ql,
           const __nv_bfloat16* __restrict__ Kh, const __nv_bfloat16* __restrict__ Kl,
           float* __restrict__ Zp)
{
    extern __shared__ __align__(16) __nv_bfloat16 smem[];
    __nv_bfloat16* Ah = smem;            // [128][72]
    __nv_bfloat16* Al = smem + 9216;
    __nv_bfloat16* Bh = smem + 18432;
    __nv_bfloat16* Bl = smem + 27648;
    __shared__ __align__(16) float srow[128][4];

    const int tid = threadIdx.x, lane = tid & 31, w = tid >> 5;
    const int wm = w >> 2, wn = w & 3;
    const int bhz = blockIdx.z, b = bhz >> 4, h = bhz & 15;
    const int m0 = blockIdx.y * 128, n0 = blockIdx.x * 128;

    const size_t qbase = (size_t)(b * 1024 + m0) * 1024 + h * 64;
    const size_t kbase = (size_t)(b * 1024 + n0) * 1024 + h * 64;

#pragma unroll
    for (int it = 0; it < 4; it++) {
        int id = tid + it * 256;
        int r = id >> 3, c = (id & 7) * 8;
        cpa16(saddr_of(Ah + r * 72 + c), Qh + qbase + (size_t)r * 1024 + c);
        cpa16(saddr_of(Al + r * 72 + c), Ql + qbase + (size_t)r * 1024 + c);
        cpa16(saddr_of(Bh + r * 72 + c), Kh + kbase + (size_t)r * 1024 + c);
        cpa16(saddr_of(Bl + r * 72 + c), Kl + kbase + (size_t)r * 1024 + c);
    }
    cpa_commit();
    cpa_wait<0>();
    __syncthreads();

    float acc[4][4][4] = {};
#pragma unroll
    for (int ks = 0; ks < 64; ks += 16) {
        uint32_t ah[4][4], al[4][4], bh[4][2], bl[4][2];
#pragma unroll
        for (int mt = 0; mt < 4; mt++) {
            int row = wm * 64 + mt * 16 + (lane & 15);
            int col = ks + ((lane >> 4) << 3);
            ldsm4(ah[mt], saddr_of(Ah + row * 72 + col));
            ldsm4(al[mt], saddr_of(Al + row * 72 + col));
        }
#pragma unroll
        for (int p = 0; p < 2; p++) {
            int row = wn * 32 + p * 16 + ((lane >> 4) << 3) + (lane & 7);
            int col = ks + (((lane >> 3) & 1) << 3);
            uint32_t t4[4];
            ldsm4(t4, saddr_of(Bh + row * 72 + col));
            bh[p * 2][0] = t4[0]; bh[p * 2][1] = t4[1];
            bh[p * 2 + 1][0] = t4[2]; bh[p * 2 + 1][1] = t4[3];
            ldsm4(t4, saddr_of(Bl + row * 72 + col));
            bl[p * 2][0] = t4[0]; bl[p * 2][1] = t4[1];
            bl[p * 2 + 1][0] = t4[2]; bl[p * 2 + 1][1] = t4[3];
        }
#pragma unroll
        for (int mt = 0; mt < 4; mt++)
#pragma unroll
            for (int nt = 0; nt < 4; nt++) {
                mma16816(acc[mt][nt], ah[mt], bh[nt]);
                mma16816(acc[mt][nt], ah[mt], bl[nt]);
                mma16816(acc[mt][nt], al[mt], bh[nt]);
            }
    }

#pragma unroll
    for (int mt = 0; mt < 4; mt++)
#pragma unroll
        for (int nt = 0; nt < 4; nt++)
#pragma unroll
            for (int q = 0; q < 4; q++)
                acc[mt][nt][q] = __expf(acc[mt][nt][q] * 0.125f);

    const int gr = lane >> 2;

#pragma unroll
    for (int mt = 0; mt < 4; mt++) {
        float s_lo = 0.f, s_hi = 0.f;
#pragma unroll
        for (int nt = 0; nt < 4; nt++) {
            s_lo += acc[mt][nt][0] + acc[mt][nt][1];
            s_hi += acc[mt][nt][2] + acc[mt][nt][3];
        }
        s_lo += __shfl_xor_sync(0xffffffffu, s_lo, 1);
        s_lo += __shfl_xor_sync(0xffffffffu, s_lo, 2);
        s_hi += __shfl_xor_sync(0xffffffffu, s_hi, 1);
        s_hi += __shfl_xor_sync(0xffffffffu, s_hi, 2);
        if ((lane & 3) == 0) {
            srow[wm * 64 + mt * 16 + gr][wn]     = s_lo;
            srow[wm * 64 + mt * 16 + gr + 8][wn] = s_hi;
        }
    }
    __syncthreads();
    if (tid < 128) {
        float zp = srow[tid][0] + srow[tid][1] + srow[tid][2] + srow[tid][3];
        Zp[((size_t)(bhz << 10) + m0 + tid) * 8 + (n0 >> 7)] = zp;
    }
}

// =============================================================================
// K3: fused zred+vscale. One warp per (bh,j) row.
// =============================================================================
__global__ void __launch_bounds__(256)
zvscale_kernel(const __nv_bfloat16* __restrict__ Vh, const __nv_bfloat16* __restrict__ Vl,
               const float* __restrict__ Zp,
               __nv_bfloat16* __restrict__ Ph, __nv_bfloat16* __restrict__ Pl)
{
    int wid = blockIdx.x * 8 + (threadIdx.x >> 5);   // 0 .. 131071 (bh*1024 + j)
    int lane = threadIdx.x & 31;
    int bh = wid >> 10, j = wid & 1023;
    int b = bh >> 4, h = bh & 15;

    float zpart = (lane < 8) ? Zp[(size_t)wid * 8 + lane] : 0.f;
    zpart += __shfl_xor_sync(0xffffffffu, zpart, 4);
    zpart += __shfl_xor_sync(0xffffffffu, zpart, 2);
    zpart += __shfl_xor_sync(0xffffffffu, zpart, 1);
    float inv = 1.f / __shfl_sync(0xffffffffu, zpart, 0);

    size_t src = (size_t)(b * 1024 + j) * 1024 + h * 64 + lane * 2;
    __nv_bfloat162 vh2 = *(const __nv_bfloat162*)(Vh + src);
    __nv_bfloat162 vl2 = *(const __nv_bfloat162*)(Vl + src);
    float v0 = (__bfloat162float(__low2bfloat16(vh2)) + __bfloat162float(__low2bfloat16(vl2))) * inv;
    float v1 = (__bfloat162float(__high2bfloat16(vh2)) + __bfloat162float(__high2bfloat16(vl2))) * inv;
    __nv_bfloat16 h0, l0, h1, l1;
    split2(v0, h0, l0);
    split2(v1, h1, l1);
    size_t dst = (size_t)wid * 64 + lane * 2;
    *(__nv_bfloat162*)(Ph + dst) = __halves2bfloat162(h0, h1);
    *(__nv_bfloat162*)(Pl + dst) = __halves2bfloat162(l0, l1);
}

// =============================================================================
// K4: fused out, j-chunk = 32 (R13 config).
//     out[i,d] = sum_{j<=i} exp(s[j,i]) * V'[j,d].
// =============================================================================
__global__ void __launch_bounds__(256)
fused_out(const __nv_bfloat16* __restrict__ Qh, const __nv_bfloat16* __restrict__ Ql,
          const __nv_bfloat16* __restrict__ Kh, const __nv_bfloat16* __restrict__ Kl,
          const __nv_bfloat16* __restrict__ Vh, const __nv_bfloat16* __restrict__ Vl,
          float* __restrict__ Out)
{
    extern __shared__ __align__(16) __nv_bfloat16 smem[];
    // K tile: hi @0, lo @9216   ([128][72])
    // Q stages: base 18432, stage s at +s*4608 (hi [32][72]=2304 elems, lo +2304)
    // V stages: base 27648, same layout
    __nv_bfloat16* Ksh = smem;
    __nv_bfloat16* Ksl = smem + 9216;

    const int tid = threadIdx.x, lane = tid & 31, w = tid >> 5;
    const int bhz = blockIdx.y, b = bhz >> 4, h = bhz & 15;
    const int i0 = (7 - (int)blockIdx.x) * 128;   // longest-first

    const size_t kbase = (size_t)(b * 1024 + i0) * 1024 + h * 64;
    const size_t qrow0 = (size_t)(b * 1024) * 1024 + h * 64;
    const size_t vrow0 = (size_t)bhz << 16;       // V' compact [bh*1024 + j][64]

    const int gr = lane >> 2, gc = (lane & 3) << 1;
    const int njc = (i0 >> 5) + 4;

    // ---- load K tile ----
#pragma unroll
    for (int it = 0; it < 4; it++) {
        int id = tid + it * 256;
        int r = id >> 3, c = (id & 7) * 8;
        cpa16(saddr_of(Ksh + r * 72 + c), Kh + kbase + (size_t)r * 1024 + c);
        cpa16(saddr_of(Ksl + r * 72 + c), Kl + kbase + (size_t)r * 1024 + c);
    }

    auto load_chunk = [&](int jc, int s) {
        __nv_bfloat16* Qsh = smem + 18432 + s * 4608;
        __nv_bfloat16* Qsl = Qsh + 2304;
        __nv_bfloat16* Vsh = smem + 27648 + s * 4608;
        __nv_bfloat16* Vsl = Vsh + 2304;
        int r = tid >> 3, c = (tid & 7) * 8;        // 32 rows x 8 groups = 256
        int j0 = jc * 32;
        cpa16(saddr_of(Qsh + r * 72 + c), Qh + qrow0 + (size_t)(j0 + r) * 1024 + c);
        cpa16(saddr_of(Qsl + r * 72 + c), Ql + qrow0 + (size_t)(j0 + r) * 1024 + c);
        cpa16(saddr_of(Vsh + r * 72 + c), Vh + vrow0 + (size_t)(j0 + r) * 64 + c);
        cpa16(saddr_of(Vsl + r * 72 + c), Vl + vrow0 + (size_t)(j0 + r) * 64 + c);
        cpa_commit();
    };

    load_chunk(0, 0);       // K + chunk0 in one group
    cpa_wait<0>();
    __syncthreads();

    // hoist K A-fragments
    uint32_t kah[4][4], kal[4][4];
#pragma unroll
    for (int kd = 0; kd < 4; kd++) {
        int row = w * 16 + (lane & 15);
        int col = kd * 16 + ((lane >> 4) << 3);
        ldsm4(kah[kd], saddr_of(Ksh + row * 72 + col));
        ldsm4(kal[kd], saddr_of(Ksl + row * 72 + col));
    }

    if (njc > 1) load_chunk(1, 1);

    float acc2[8][4] = {};
    const int ibase = i0 + w * 16 + gr;

    for (int jc = 0; jc < njc; jc++) {
        const int s = jc & 1;
        cpa_wait<0>();
        __syncthreads();
        if (jc + 1 < njc) load_chunk(jc + 1, s ^ 1);

        const __nv_bfloat16* Qsh = smem + 18432 + s * 4608;
        const __nv_bfloat16* Qsl = Qsh + 2304;
        const __nv_bfloat16* Vsh = smem + 27648 + s * 4608;
        const __nv_bfloat16* Vsl = Vsh + 2304;

        // ---- mma1: S'[i (16 rows), j (32 cols)] ----
        float acc1[4][4] = {};
#pragma unroll
        for (int kd = 0; kd < 4; kd++) {
            int ks = kd * 16;
            uint32_t qbh[4][2], qbl[4][2];
#pragma unroll
            for (int p = 0; p < 2; p++) {
                int row = p * 16 + ((lane >> 4) << 3) + (lane & 7);
                int col = ks + (((lane >> 3) & 1) << 3);
                uint32_t t4[4];
                ldsm4(t4, saddr_of(Qsh + row * 72 + col));
                qbh[p * 2][0] = t4[0]; qbh[p * 2][1] = t4[1];
                qbh[p * 2 + 1][0] = t4[2]; qbh[p * 2 + 1][1] = t4[3];
                ldsm4(t4, saddr_of(Qsl + row * 72 + col));
                qbl[p * 2][0] = t4[0]; qbl[p * 2][1] = t4[1];
                qbl[p * 2 + 1][0] = t4[2]; qbl[p * 2 + 1][1] = t4[3];
            }
#pragma unroll
            for (int nt = 0; nt < 4; nt++) {
                mma16816(acc1[nt], kah[kd], qbh[nt]);
                mma16816(acc1[nt], kah[kd], qbl[nt]);
                mma16816(acc1[nt], kal[kd], qbh[nt]);
            }
        }

        // ---- exp + mask (keep j <= i) ----
        const int j0 = jc * 32;
#pragma unroll
        for (int nt = 0; nt < 4; nt++) {
            int jg = j0 + nt * 8 + gc;
#pragma unroll
            for (int q = 0; q < 4; q++) {
                int jj = jg + (q & 1);
                int ii = ibase + ((q >> 1) << 3);
                acc1[nt][q] = (jj <= ii) ? __expf(acc1[nt][q] * 0.125f) : 0.f;
            }
        }

        // ---- C-frag -> A-frag repack (split bf16) ----
        uint32_t pah[2][4], pal[2][4];
#pragma unroll
        for (int kj = 0; kj < 2; kj++) {
            const float* x0 = acc1[2 * kj];
            const float* x1 = acc1[2 * kj + 1];
            packsplit(x0[0], x0[1], pah[kj][0], pal[kj][0]);
            packsplit(x0[2], x0[3], pah[kj][1], pal[kj][1]);
            packsplit(x1[0], x1[1], pah[kj][2], pal[kj][2]);
            packsplit(x1[2], x1[3], pah[kj][3], pal[kj][3]);
        }

        // ---- mma2: out += P' * V' ----
#pragma unroll
        for (int kj = 0; kj < 2; kj++) {
            int kr = kj * 16 + (((lane >> 3) & 1) << 3) + (lane & 7);
            uint32_t vbh[8][2], vbl[8][2];
#pragma unroll
            for (int qd = 0; qd < 4; qd++) {
                int dc = qd * 16 + ((lane >> 4) << 3);
                uint32_t t4[4];
                ldsm4t(t4, saddr_of(Vsh + kr * 72 + dc));
                vbh[qd * 2][0] = t4[0]; vbh[qd * 2][1] = t4[1];
                vbh[qd * 2 + 1][0] = t4[2]; vbh[qd * 2 + 1][1] = t4[3];
                ldsm4t(t4, saddr_of(Vsl + kr * 72 + dc));
                vbl[qd * 2][0] = t4[0]; vbl[qd * 2][1] = t4[1];
                vbl[qd * 2 + 1][0] = t4[2]; vbl[qd * 2 + 1][1] = t4[3];
            }
#pragma unroll
            for (int nt2 = 0; nt2 < 8; nt2++) {
                mma16816(acc2[nt2], pah[kj], vbh[nt2]);
                mma16816(acc2[nt2], pah[kj], vbl[nt2]);
                mma16816(acc2[nt2], pal[kj], vbh[nt2]);
            }
        }
        __syncthreads();
    }

    // ---- store out ----
#pragma unroll
    for (int nt2 = 0; nt2 < 8; nt2++) {
        int d = nt2 * 8 + gc;
#pragma unroll
        for (int hf = 0; hf < 2; hf++) {
            int i = ibase + hf * 8;
            *(float2*)(Out + (size_t)(b * 1024 + i) * 1024 + h * 64 + d) =
                make_float2(acc2[nt2][hf * 2], acc2[nt2][hf * 2 + 1]);
        }
    }
}

// =============================================================================
extern "C" void kernel_launch(void* const* d_in, const int* in_sizes, int n_in,
                              void* d_out, int out_size)
{
    const float* q  = (const float*)d_in[0];
    const float* k  = (const float*)d_in[1];
    const float* v  = (const float*)d_in[2];
    const float* Wq = (const float*)d_in[3];
    const float* Wk = (const float*)d_in[4];
    const float* Wv = (const float*)d_in[5];
    float* out = (float*)d_out;
    (void)in_sizes; (void)n_in; (void)out_size;

    __nv_bfloat16 *xh, *xl, *wh, *wl, *yh, *yl, *vph, *vpl;
    float *zp;
    cudaGetSymbolAddress((void**)&xh, g_xh);
    cudaGetSymbolAddress((void**)&xl, g_xl);
    cudaGetSymbolAddress((void**)&wh, g_wh);
    cudaGetSymbolAddress((void**)&wl, g_wl);
    cudaGetSymbolAddress((void**)&yh, g_yh);
    cudaGetSymbolAddress((void**)&yl, g_yl);
    cudaGetSymbolAddress((void**)&zp, g_zp);
    cudaGetSymbolAddress((void**)&vph, g_vph);
    cudaGetSymbolAddress((void**)&vpl, g_vpl);

    cudaFuncSetAttribute(proj_mma,   cudaFuncAttributeMaxDynamicSharedMemorySize, 81920);
    cudaFuncSetAttribute(zscore_mma, cudaFuncAttributeMaxDynamicSharedMemorySize, 73728);
    cudaFuncSetAttribute(fused_out,  cudaFuncAttributeMaxDynamicSharedMemorySize, 73728);

    split3_kernel<<<dim3(XN / 1024, 3), 256>>>(q, k, v, xh, xl, (size_t)XN);
    split3_kernel<<<dim3(WN / 1024, 3), 256>>>(Wq, Wk, Wv, wh, wl, (size_t)WN);

    proj_mma<<<dim3(8, 64, 3), 256, 81920>>>(xh, xl, wh, wl, yh, yl);

    dim3 sgrid(8, 8, BATCH * NHEADS);
    zscore_mma<<<sgrid, 256, 73728>>>(yh, yl, yh + XN, yl + XN, zp);

    zvscale_kernel<<<16384, 256>>>(yh + 2 * XN, yl + 2 * XN, zp, vph, vpl);

    fused_out<<<dim3(8, BATCH * NHEADS), 256, 73728>>>(
        yh, yl, yh + XN, yl + XN, vph, vpl, out);
}

// round 16
// speedup vs baseline: 1.0214x; 1.0013x over previous
#include <cuda_runtime.h>
#include <cuda_bf16.h>
#include <stdint.h>

#define BATCH 8
#define SEQ 1024
#define HID 1024
#define NHEADS 16
#define DK 64

#define XN 8388608   // 8192*1024
#define WN 1048576   // 1024*1024

// ---------------- scratch (static __device__ — no allocs allowed) -------------
__device__ __align__(16) __nv_bfloat16 g_xh[3 * XN];
__device__ __align__(16) __nv_bfloat16 g_xl[3 * XN];
__device__ __align__(16) __nv_bfloat16 g_wh[3 * WN];
__device__ __align__(16) __nv_bfloat16 g_wl[3 * WN];
__device__ __align__(16) __nv_bfloat16 g_yh[3 * XN];
__device__ __align__(16) __nv_bfloat16 g_yl[3 * XN];
__device__ __align__(16) float g_zp[128 * 1024 * 8];
__device__ __align__(16) __nv_bfloat16 g_vph[128 * 65536];  // V' = V/Z, [bh][j][64] hi
__device__ __align__(16) __nv_bfloat16 g_vpl[128 * 65536];  // lo

// ---------------- helpers ----------------------------------------------------
__device__ __forceinline__ uint32_t saddr_of(const void* p) {
    return (uint32_t)__cvta_generic_to_shared(p);
}
__device__ __forceinline__ void cpa16(uint32_t dst, const void* src) {
    asm volatile("cp.async.cg.shared.global [%0], [%1], 16;" :: "r"(dst), "l"(src));
}
__device__ __forceinline__ void cpa_commit() {
    asm volatile("cp.async.commit_group;");
}
template <int N>
__device__ __forceinline__ void cpa_wait() {
    asm volatile("cp.async.wait_group %0;" :: "n"(N));
}
__device__ __forceinline__ void ldsm4(uint32_t r[4], uint32_t a) {
    asm volatile("ldmatrix.sync.aligned.m8n8.x4.shared.b16 {%0,%1,%2,%3}, [%4];"
                 : "=r"(r[0]), "=r"(r[1]), "=r"(r[2]), "=r"(r[3]) : "r"(a));
}
__device__ __forceinline__ void ldsm4t(uint32_t r[4], uint32_t a) {
    asm volatile("ldmatrix.sync.aligned.m8n8.x4.trans.shared.b16 {%0,%1,%2,%3}, [%4];"
                 : "=r"(r[0]), "=r"(r[1]), "=r"(r[2]), "=r"(r[3]) : "r"(a));
}
__device__ __forceinline__ void mma16816(float* c, const uint32_t* a, const uint32_t* b) {
    asm volatile("mma.sync.aligned.m16n8k16.row.col.f32.bf16.bf16.f32 "
                 "{%0,%1,%2,%3}, {%4,%5,%6,%7}, {%8,%9}, {%0,%1,%2,%3};"
                 : "+f"(c[0]), "+f"(c[1]), "+f"(c[2]), "+f"(c[3])
                 : "r"(a[0]), "r"(a[1]), "r"(a[2]), "r"(a[3]), "r"(b[0]), "r"(b[1]));
}
__device__ __forceinline__ void split2(float x, __nv_bfloat16& h, __nv_bfloat16& l) {
    h = __float2bfloat16(x);
    l = __float2bfloat16(x - __bfloat162float(h));
}
__device__ __forceinline__ void packsplit(float a, float b, uint32_t& hh, uint32_t& ll) {
    __nv_bfloat16 h0, l0, h1, l1;
    split2(a, h0, l0);
    split2(b, h1, l1);
    __nv_bfloat162 H = __halves2bfloat162(h0, h1), L = __halves2bfloat162(l0, l1);
    hh = *(uint32_t*)&H;
    ll = *(uint32_t*)&L;
}

// =============================================================================
// K0: elementwise fp32 -> split bf16 hi/lo; grid.y selects one of 3 inputs.
// =============================================================================
__global__ void __launch_bounds__(256)
split3_kernel(const float* __restrict__ X0, const float* __restrict__ X1,
              const float* __restrict__ X2, __nv_bfloat16* __restrict__ H,
              __nv_bfloat16* __restrict__ L, size_t span)
{
    const float* X = (blockIdx.y == 0) ? X0 : (blockIdx.y == 1) ? X1 : X2;
    size_t base = (size_t)blockIdx.y * span;
    size_t i = ((size_t)blockIdx.x * 256 + threadIdx.x) * 4;
    float4 v = *(const float4*)(X + i);
    __nv_bfloat16 h[4], l[4];
    split2(v.x, h[0], l[0]); split2(v.y, h[1], l[1]);
    split2(v.z, h[2], l[2]); split2(v.w, h[3], l[3]);
    *(__nv_bfloat162*)(H + base + i)     = __halves2bfloat162(h[0], h[1]);
    *(__nv_bfloat162*)(H + base + i + 2) = __halves2bfloat162(h[2], h[3]);
    *(__nv_bfloat162*)(L + base + i)     = __halves2bfloat162(l[0], l[1]);
    *(__nv_bfloat162*)(L + base + i + 2) = __halves2bfloat162(l[2], l[3]);
}

// =============================================================================
// K1: projection  Y[m,n] = sum_k X[m,k] * W[n,k]  (z = q/k/v)
//     cp.async 2-stage pipeline, 80KB dyn smem.
// =============================================================================
__global__ void __launch_bounds__(256)
proj_mma(const __nv_bfloat16* __restrict__ Xh, const __nv_bfloat16* __restrict__ Xl,
         const __nv_bfloat16* __restrict__ Wh, const __nv_bfloat16* __restrict__ Wl,
         __nv_bfloat16* __restrict__ Yh, __nv_bfloat16* __restrict__ Yl)
{
    extern __shared__ __align__(16) __nv_bfloat16 smem[];

    const int tid = threadIdx.x, lane = tid & 31, w = tid >> 5;
    const int wm = w >> 2, wn = w & 3;
    const int z = blockIdx.z;
    const size_t xoff = (size_t)z * XN, woff = (size_t)z * WN;
    Xh += xoff; Xl += xoff; Yh += xoff; Yl += xoff; Wh += woff; Wl += woff;
    const int m0 = blockIdx.y * 128, n0 = blockIdx.x * 128;

    const int lr = tid >> 2, lc = (tid & 3) * 8;

    float acc[4][4][4] = {};

#define STG(s, off) (smem + (s) * 20480 + (off))
    auto load_stage = [&](int s, int k0) {
#pragma unroll
        for (int q = 0; q < 2; q++) {
            int r = lr + q * 64;
            cpa16(saddr_of(STG(s, 0)     + r * 40 + lc), Xh + (size_t)(m0 + r) * 1024 + k0 + lc);
            cpa16(saddr_of(STG(s, 5120)  + r * 40 + lc), Xl + (size_t)(m0 + r) * 1024 + k0 + lc);
            cpa16(saddr_of(STG(s, 10240) + r * 40 + lc), Wh + (size_t)(n0 + r) * 1024 + k0 + lc);
            cpa16(saddr_of(STG(s, 15360) + r * 40 + lc), Wl + (size_t)(n0 + r) * 1024 + k0 + lc);
        }
    };

    load_stage(0, 0);
    cpa_commit();

    for (int it = 0; it < 32; it++) {
        const int cur = it & 1;
        if (it + 1 < 32) {
            load_stage(cur ^ 1, (it + 1) * 32);
            cpa_commit();
            cpa_wait<1>();
        } else {
            cpa_wait<0>();
        }
        __syncthreads();

        const __nv_bfloat16* Ah = STG(cur, 0);
        const __nv_bfloat16* Al = STG(cur, 5120);
        const __nv_bfloat16* Bh = STG(cur, 10240);
        const __nv_bfloat16* Bl = STG(cur, 15360);

#pragma unroll
        for (int ks = 0; ks < 32; ks += 16) {
            uint32_t ah[4][4], al[4][4], bh[4][2], bl[4][2];
#pragma unroll
            for (int mt = 0; mt < 4; mt++) {
                int row = wm * 64 + mt * 16 + (lane & 15);
                int col = ks + ((lane >> 4) << 3);
                ldsm4(ah[mt], saddr_of(Ah + row * 40 + col));
                ldsm4(al[mt], saddr_of(Al + row * 40 + col));
            }
#pragma unroll
            for (int p = 0; p < 2; p++) {
                int row = wn * 32 + p * 16 + ((lane >> 4) << 3) + (lane & 7);
                int col = ks + (((lane >> 3) & 1) << 3);
                uint32_t t4[4];
                ldsm4(t4, saddr_of(Bh + row * 40 + col));
                bh[p * 2][0] = t4[0]; bh[p * 2][1] = t4[1];
                bh[p * 2 + 1][0] = t4[2]; bh[p * 2 + 1][1] = t4[3];
                ldsm4(t4, saddr_of(Bl + row * 40 + col));
                bl[p * 2][0] = t4[0]; bl[p * 2][1] = t4[1];
                bl[p * 2 + 1][0] = t4[2]; bl[p * 2 + 1][1] = t4[3];
            }
#pragma unroll
            for (int mt = 0; mt < 4; mt++)
#pragma unroll
                for (int nt = 0; nt < 4; nt++) {
                    mma16816(acc[mt][nt], ah[mt], bh[nt]);
                    mma16816(acc[mt][nt], ah[mt], bl[nt]);
                    mma16816(acc[mt][nt], al[mt], bh[nt]);
                }
        }
        __syncthreads();
    }
#undef STG

    const int gr = lane >> 2, gc = (lane & 3) << 1;
#pragma unroll
    for (int mt = 0; mt < 4; mt++)
#pragma unroll
        for (int nt = 0; nt < 4; nt++) {
            int m = m0 + wm * 64 + mt * 16 + gr;
            int n = n0 + wn * 32 + nt * 8 + gc;
#pragma unroll
            for (int hf = 0; hf < 2; hf++) {
                float c0 = acc[mt][nt][hf * 2], c1 = acc[mt][nt][hf * 2 + 1];
                __nv_bfloat16 h0, l0, h1, l1;
                split2(c0, h0, l0);
                split2(c1, h1, l1);
                size_t off = (size_t)(m + hf * 8) * 1024 + n;
                *(__nv_bfloat162*)(Yh + off) = __halves2bfloat162(h0, h1);
                *(__nv_bfloat162*)(Yl + off) = __halves2bfloat162(l0, l1);
            }
        }
}

// =============================================================================
// K2: zscore — S = QK^T, exp, deterministic row-sum partials ONLY (no E write).
// =============================================================================
__global__ void __launch_bounds__(256)
zscore_mma(const __nv_bfloat16* __restrict__ Qh, const __nv_bfloat16* __restrict__ Ql,
           const __nv_bfloat16* __restrict__ Kh, const __nv_bfloat16* __restrict__ Kl,
           float* __restrict__ Zp)
{
    extern __shared__ __align__(16) __nv_bfloat16 smem[];
    __nv_bfloat16* Ah = smem;            // [128][72]
    __nv_bfloat16* Al = smem + 9216;
    __nv_bfloat16* Bh = smem + 18432;
    __nv_bfloat16* Bl = smem + 27648;
    __shared__ __align__(16) float srow[128][4];

    const int tid = threadIdx.x, lane = tid & 31, w = tid >> 5;
    const int wm = w >> 2, wn = w & 3;
    const int bhz = blockIdx.z, b = bhz >> 4, h = bhz & 15;
    const int m0 = blockIdx.y * 128, n0 = blockIdx.x * 128;

    const size_t qbase = (size_t)(b * 1024 + m0) * 1024 + h * 64;
    const size_t kbase = (size_t)(b * 1024 + n0) * 1024 + h * 64;

#pragma unroll
    for (int it = 0; it < 4; it++) {
        int id = tid + it * 256;
        int r = id >> 3, c = (id & 7) * 8;
        cpa16(saddr_of(Ah + r * 72 + c), Qh + qbase + (size_t)r * 1024 + c);
        cpa16(saddr_of(Al + r * 72 + c), Ql + qbase + (size_t)r * 1024 + c);
        cpa16(saddr_of(Bh + r * 72 + c), Kh + kbase + (size_t)r * 1024 + c);
        cpa16(saddr_of(Bl + r * 72 + c), Kl + kbase + (size_t)r * 1024 + c);
    }
    cpa_commit();
    cpa_wait<0>();
    __syncthreads();

    float acc[4][4][4] = {};
#pragma unroll
    for (int ks = 0; ks < 64; ks += 16) {
        uint32_t ah[4][4], al[4][4], bh[4][2], bl[4][2];
#pragma unroll
        for (int mt = 0; mt < 4; mt++) {
            int row = wm * 64 + mt * 16 + (lane & 15);
            int col = ks + ((lane >> 4) << 3);
            ldsm4(ah[mt], saddr_of(Ah + row * 72 + col));
            ldsm4(al[mt], saddr_of(Al + row * 72 + col));
        }
#pragma unroll
        for (int p = 0; p < 2; p++) {
            int row = wn * 32 + p * 16 + ((lane >> 4) << 3) + (lane & 7);
            int col = ks + (((lane >> 3) & 1) << 3);
            uint32_t t4[4];
            ldsm4(t4, saddr_of(Bh + row * 72 + col));
            bh[p * 2][0] = t4[0]; bh[p * 2][1] = t4[1];
            bh[p * 2 + 1][0] = t4[2]; bh[p * 2 + 1][1] = t4[3];
            ldsm4(t4, saddr_of(Bl + row * 72 + col));
            bl[p * 2][0] = t4[0]; bl[p * 2][1] = t4[1];
            bl[p * 2 + 1][0] = t4[2]; bl[p * 2 + 1][1] = t4[3];
        }
#pragma unroll
        for (int mt = 0; mt < 4; mt++)
#pragma unroll
            for (int nt = 0; nt < 4; nt++) {
                mma16816(acc[mt][nt], ah[mt], bh[nt]);
                mma16816(acc[mt][nt], ah[mt], bl[nt]);
                mma16816(acc[mt][nt], al[mt], bh[nt]);
            }
    }

#pragma unroll
    for (int mt = 0; mt < 4; mt++)
#pragma unroll
        for (int nt = 0; nt < 4; nt++)
#pragma unroll
            for (int q = 0; q < 4; q++)
                acc[mt][nt][q] = __expf(acc[mt][nt][q] * 0.125f);

    const int gr = lane >> 2;

#pragma unroll
    for (int mt = 0; mt < 4; mt++) {
        float s_lo = 0.f, s_hi = 0.f;
#pragma unroll
        for (int nt = 0; nt < 4; nt++) {
            s_lo += acc[mt][nt][0] + acc[mt][nt][1];
            s_hi += acc[mt][nt][2] + acc[mt][nt][3];
        }
        s_lo += __shfl_xor_sync(0xffffffffu, s_lo, 1);
        s_lo += __shfl_xor_sync(0xffffffffu, s_lo, 2);
        s_hi += __shfl_xor_sync(0xffffffffu, s_hi, 1);
        s_hi += __shfl_xor_sync(0xffffffffu, s_hi, 2);
        if ((lane & 3) == 0) {
            srow[wm * 64 + mt * 16 + gr][wn]     = s_lo;
            srow[wm * 64 + mt * 16 + gr + 8][wn] = s_hi;
        }
    }
    __syncthreads();
    if (tid < 128) {
        float zp = srow[tid][0] + srow[tid][1] + srow[tid][2] + srow[tid][3];
        Zp[((size_t)(bhz << 10) + m0 + tid) * 8 + (n0 >> 7)] = zp;
    }
}

// =============================================================================
// K3: fused zred+vscale. One warp per (bh,j) row.
// =============================================================================
__global__ void __launch_bounds__(256)
zvscale_kernel(const __nv_bfloat16* __restrict__ Vh, const __nv_bfloat16* __restrict__ Vl,
               const float* __restrict__ Zp,
               __nv_bfloat16* __restrict__ Ph, __nv_bfloat16* __restrict__ Pl)
{
    int wid = blockIdx.x * 8 + (threadIdx.x >> 5);   // 0 .. 131071 (bh*1024 + j)
    int lane = threadIdx.x & 31;
    int bh = wid >> 10, j = wid & 1023;
    int b = bh >> 4, h = bh & 15;

    float zpart = (lane < 8) ? Zp[(size_t)wid * 8 + lane] : 0.f;
    zpart += __shfl_xor_sync(0xffffffffu, zpart, 4);
    zpart += __shfl_xor_sync(0xffffffffu, zpart, 2);
    zpart += __shfl_xor_sync(0xffffffffu, zpart, 1);
    float inv = 1.f / __shfl_sync(0xffffffffu, zpart, 0);

    size_t src = (size_t)(b * 1024 + j) * 1024 + h * 64 + lane * 2;
    __nv_bfloat162 vh2 = *(const __nv_bfloat162*)(Vh + src);
    __nv_bfloat162 vl2 = *(const __nv_bfloat162*)(Vl + src);
    float v0 = (__bfloat162float(__low2bfloat16(vh2)) + __bfloat162float(__low2bfloat16(vl2))) * inv;
    float v1 = (__bfloat162float(__high2bfloat16(vh2)) + __bfloat162float(__high2bfloat16(vl2))) * inv;
    __nv_bfloat16 h0, l0, h1, l1;
    split2(v0, h0, l0);
    split2(v1, h1, l1);
    size_t dst = (size_t)wid * 64 + lane * 2;
    *(__nv_bfloat162*)(Ph + dst) = __halves2bfloat162(h0, h1);
    *(__nv_bfloat162*)(Pl + dst) = __halves2bfloat162(l0, l1);
}

// =============================================================================
// K4: fused out, j-chunk = 32, 2 CTAs/SM (regs capped at 128; K frags
//     reloaded per chunk from resident smem tile instead of hoisted).
//     out[i,d] = sum_{j<=i} exp(s[j,i]) * V'[j,d].
// =============================================================================
__global__ void __launch_bounds__(256, 2)
fused_out(const __nv_bfloat16* __restrict__ Qh, const __nv_bfloat16* __restrict__ Ql,
          const __nv_bfloat16* __restrict__ Kh, const __nv_bfloat16* __restrict__ Kl,
          const __nv_bfloat16* __restrict__ Vh, const __nv_bfloat16* __restrict__ Vl,
          float* __restrict__ Out)
{
    extern __shared__ __align__(16) __nv_bfloat16 smem[];
    // K tile: hi @0, lo @9216   ([128][72])
    // Q stages: base 18432, stage s at +s*4608 (hi [32][72]=2304 elems, lo +2304)
    // V stages: base 27648, same layout
    __nv_bfloat16* Ksh = smem;
    __nv_bfloat16* Ksl = smem + 9216;

    const int tid = threadIdx.x, lane = tid & 31, w = tid >> 5;
    const int bhz = blockIdx.y, b = bhz >> 4, h = bhz & 15;
    const int i0 = (7 - (int)blockIdx.x) * 128;   // longest-first

    const size_t kbase = (size_t)(b * 1024 + i0) * 1024 + h * 64;
    const size_t qrow0 = (size_t)(b * 1024) * 1024 + h * 64;
    const size_t vrow0 = (size_t)bhz << 16;       // V' compact [bh*1024 + j][64]

    const int gr = lane >> 2, gc = (lane & 3) << 1;
    const int njc = (i0 >> 5) + 4;

    // ---- load K tile ----
#pragma unroll
    for (int it = 0; it < 4; it++) {
        int id = tid + it * 256;
        int r = id >> 3, c = (id & 7) * 8;
        cpa16(saddr_of(Ksh + r * 72 + c), Kh + kbase + (size_t)r * 1024 + c);
        cpa16(saddr_of(Ksl + r * 72 + c), Kl + kbase + (size_t)r * 1024 + c);
    }

    auto load_chunk = [&](int jc, int s) {
        __nv_bfloat16* Qsh = smem + 18432 + s * 4608;
        __nv_bfloat16* Qsl = Qsh + 2304;
        __nv_bfloat16* Vsh = smem + 27648 + s * 4608;
        __nv_bfloat16* Vsl = Vsh + 2304;
        int r = tid >> 3, c = (tid & 7) * 8;        // 32 rows x 8 groups = 256
        int j0 = jc * 32;
        cpa16(saddr_of(Qsh + r * 72 + c), Qh + qrow0 + (size_t)(j0 + r) * 1024 + c);
        cpa16(saddr_of(Qsl + r * 72 + c), Ql + qrow0 + (size_t)(j0 + r) * 1024 + c);
        cpa16(saddr_of(Vsh + r * 72 + c), Vh + vrow0 + (size_t)(j0 + r) * 64 + c);
        cpa16(saddr_of(Vsl + r * 72 + c), Vl + vrow0 + (size_t)(j0 + r) * 64 + c);
        cpa_commit();
    };

    load_chunk(0, 0);       // K + chunk0 in one group
    cpa_wait<0>();
    __syncthreads();

    if (njc > 1) load_chunk(1, 1);

    float acc2[8][4] = {};
    const int ibase = i0 + w * 16 + gr;

    for (int jc = 0; jc < njc; jc++) {
        const int s = jc & 1;
        cpa_wait<0>();
        __syncthreads();
        if (jc + 1 < njc) load_chunk(jc + 1, s ^ 1);

        const __nv_bfloat16* Qsh = smem + 18432 + s * 4608;
        const __nv_bfloat16* Qsl = Qsh + 2304;
        const __nv_bfloat16* Vsh = smem + 27648 + s * 4608;
        const __nv_bfloat16* Vsl = Vsh + 2304;

        // ---- mma1: S'[i (16 rows), j (32 cols)] ----
        float acc1[4][4] = {};
#pragma unroll
        for (int kd = 0; kd < 4; kd++) {
            int ks = kd * 16;
            // K A-fragments reloaded per chunk (frees 32 regs for 2 CTA/SM)
            uint32_t kah[4], kal[4];
            {
                int row = w * 16 + (lane & 15);
                int col = ks + ((lane >> 4) << 3);
                ldsm4(kah, saddr_of(Ksh + row * 72 + col));
                ldsm4(kal, saddr_of(Ksl + row * 72 + col));
            }
            uint32_t qbh[4][2], qbl[4][2];
#pragma unroll
            for (int p = 0; p < 2; p++) {
                int row = p * 16 + ((lane >> 4) << 3) + (lane & 7);
                int col = ks + (((lane >> 3) & 1) << 3);
                uint32_t t4[4];
                ldsm4(t4, saddr_of(Qsh + row * 72 + col));
                qbh[p * 2][0] = t4[0]; qbh[p * 2][1] = t4[1];
                qbh[p * 2 + 1][0] = t4[2]; qbh[p * 2 + 1][1] = t4[3];
                ldsm4(t4, saddr_of(Qsl + row * 72 + col));
                qbl[p * 2][0] = t4[0]; qbl[p * 2][1] = t4[1];
                qbl[p * 2 + 1][0] = t4[2]; qbl[p * 2 + 1][1] = t4[3];
            }
#pragma unroll
            for (int nt = 0; nt < 4; nt++) {
                mma16816(acc1[nt], kah, qbh[nt]);
                mma16816(acc1[nt], kah, qbl[nt]);
                mma16816(acc1[nt], kal, qbh[nt]);
            }
        }

        // ---- exp + mask (keep j <= i) ----
        const int j0 = jc * 32;
#pragma unroll
        for (int nt = 0; nt < 4; nt++) {
            int jg = j0 + nt * 8 + gc;
#pragma unroll
            for (int q = 0; q < 4; q++) {
                int jj = jg + (q & 1);
                int ii = ibase + ((q >> 1) << 3);
                acc1[nt][q] = (jj <= ii) ? __expf(acc1[nt][q] * 0.125f) : 0.f;
            }
        }

        // ---- C-frag -> A-frag repack (split bf16) ----
        uint32_t pah[2][4], pal[2][4];
#pragma unroll
        for (int kj = 0; kj < 2; kj++) {
            const float* x0 = acc1[2 * kj];
            const float* x1 = acc1[2 * kj + 1];
            packsplit(x0[0], x0[1], pah[kj][0], pal[kj][0]);
            packsplit(x0[2], x0[3], pah[kj][1], pal[kj][1]);
            packsplit(x1[0], x1[1], pah[kj][2], pal[kj][2]);
            packsplit(x1[2], x1[3], pah[kj][3], pal[kj][3]);
        }

        // ---- mma2: out += P' * V' ----
#pragma unroll
        for (int kj = 0; kj < 2; kj++) {
            int kr = kj * 16 + (((lane >> 3) & 1) << 3) + (lane & 7);
            uint32_t vbh[8][2], vbl[8][2];
#pragma unroll
            for (int qd = 0; qd < 4; qd++) {
                int dc = qd * 16 + ((lane >> 4) << 3);
                uint32_t t4[4];
                ldsm4t(t4, saddr_of(Vsh + kr * 72 + dc));
                vbh[qd * 2][0] = t4[0]; vbh[qd * 2][1] = t4[1];
                vbh[qd * 2 + 1][0] = t4[2]; vbh[qd * 2 + 1][1] = t4[3];
                ldsm4t(t4, saddr_of(Vsl + kr * 72 + dc));
                vbl[qd * 2][0] = t4[0]; vbl[qd * 2][1] = t4[1];
                vbl[qd * 2 + 1][0] = t4[2]; vbl[qd * 2 + 1][1] = t4[3];
            }
#pragma unroll
            for (int nt2 = 0; nt2 < 8; nt2++) {
                mma16816(acc2[nt2], pah[kj], vbh[nt2]);
                mma16816(acc2[nt2], pah[kj], vbl[nt2]);
                mma16816(acc2[nt2], pal[kj], vbh[nt2]);
            }
        }
        __syncthreads();
    }

    // ---- store out ----
#pragma unroll
    for (int nt2 = 0; nt2 < 8; nt2++) {
        int d = nt2 * 8 + gc;
#pragma unroll
        for (int hf = 0; hf < 2; hf++) {
            int i = ibase + hf * 8;
            *(float2*)(Out + (size_t)(b * 1024 + i) * 1024 + h * 64 + d) =
                make_float2(acc2[nt2][hf * 2], acc2[nt2][hf * 2 + 1]);
        }
    }
}

// =============================================================================
extern "C" void kernel_launch(void* const* d_in, const int* in_sizes, int n_in,
                              void* d_out, int out_size)
{
    const float* q  = (const float*)d_in[0];
    const float* k  = (const float*)d_in[1];
    const float* v  = (const float*)d_in[2];
    const float* Wq = (const float*)d_in[3];
    const float* Wk = (const float*)d_in[4];
    const float* Wv = (const float*)d_in[5];
    float* out = (float*)d_out;
    (void)in_sizes; (void)n_in; (void)out_size;

    __nv_bfloat16 *xh, *xl, *wh, *wl, *yh, *yl, *vph, *vpl;
    float *zp;
    cudaGetSymbolAddress((void**)&xh, g_xh);
    cudaGetSymbolAddress((void**)&xl, g_xl);
    cudaGetSymbolAddress((void**)&wh, g_wh);
    cudaGetSymbolAddress((void**)&wl, g_wl);
    cudaGetSymbolAddress((void**)&yh, g_yh);
    cudaGetSymbolAddress((void**)&yl, g_yl);
    cudaGetSymbolAddress((void**)&zp, g_zp);
    cudaGetSymbolAddress((void**)&vph, g_vph);
    cudaGetSymbolAddress((void**)&vpl, g_vpl);

    cudaFuncSetAttribute(proj_mma,   cudaFuncAttributeMaxDynamicSharedMemorySize, 81920);
    cudaFuncSetAttribute(zscore_mma, cudaFuncAttributeMaxDynamicSharedMemorySize, 73728);
    cudaFuncSetAttribute(fused_out,  cudaFuncAttributeMaxDynamicSharedMemorySize, 73728);

    split3_kernel<<<dim3(XN / 1024, 3), 256>>>(q, k, v, xh, xl, (size_t)XN);
    split3_kernel<<<dim3(WN / 1024, 3), 256>>>(Wq, Wk, Wv, wh, wl, (size_t)WN);

    proj_mma<<<dim3(8, 64, 3), 256, 81920>>>(xh, xl, wh, wl, yh, yl);

    dim3 sgrid(8, 8, BATCH * NHEADS);
    zscore_mma<<<sgrid, 256, 73728>>>(yh, yl, yh + XN, yl + XN, zp);

    zvscale_kernel<<<16384, 256>>>(yh + 2 * XN, yl + 2 * XN, zp, vph, vpl);

    fused_out<<<dim3(8, BATCH * NHEADS), 256, 73728>>>(
        yh, yl, yh + XN, yl + XN, vph, vpl, out);
}

// round 17
// speedup vs baseline: 1.0371x; 1.0153x over previous
#include <cuda_runtime.h>
#include <cuda_bf16.h>
#include <stdint.h>

#define BATCH 8
#define SEQ 1024
#define HID 1024
#define NHEADS 16
#define DK 64

#define XN 8388608   // 8192*1024
#define WN 1048576   // 1024*1024

// ---------------- scratch (static __device__ — no allocs allowed) -------------
__device__ __align__(16) __nv_bfloat16 g_xh[3 * XN];
__device__ __align__(16) __nv_bfloat16 g_xl[3 * XN];
__device__ __align__(16) __nv_bfloat16 g_wh[3 * WN];
__device__ __align__(16) __nv_bfloat16 g_wl[3 * WN];
__device__ __align__(16) __nv_bfloat16 g_yh[3 * XN];
__device__ __align__(16) __nv_bfloat16 g_yl[3 * XN];
__device__ __align__(16) float g_zp[128 * 1024 * 8];
__device__ __align__(16) __nv_bfloat16 g_vph[128 * 65536];  // V' = V/Z, [bh][j][64] hi
__device__ __align__(16) __nv_bfloat16 g_vpl[128 * 65536];  // lo

// ---------------- helpers ----------------------------------------------------
__device__ __forceinline__ uint32_t saddr_of(const void* p) {
    return (uint32_t)__cvta_generic_to_shared(p);
}
__device__ __forceinline__ void cpa16(uint32_t dst, const void* src) {
    asm volatile("cp.async.cg.shared.global [%0], [%1], 16;" :: "r"(dst), "l"(src));
}
__device__ __forceinline__ void cpa_commit() {
    asm volatile("cp.async.commit_group;");
}
template <int N>
__device__ __forceinline__ void cpa_wait() {
    asm volatile("cp.async.wait_group %0;" :: "n"(N));
}
__device__ __forceinline__ void ldsm4(uint32_t r[4], uint32_t a) {
    asm volatile("ldmatrix.sync.aligned.m8n8.x4.shared.b16 {%0,%1,%2,%3}, [%4];"
                 : "=r"(r[0]), "=r"(r[1]), "=r"(r[2]), "=r"(r[3]) : "r"(a));
}
__device__ __forceinline__ void ldsm4t(uint32_t r[4], uint32_t a) {
    asm volatile("ldmatrix.sync.aligned.m8n8.x4.trans.shared.b16 {%0,%1,%2,%3}, [%4];"
                 : "=r"(r[0]), "=r"(r[1]), "=r"(r[2]), "=r"(r[3]) : "r"(a));
}
__device__ __forceinline__ void mma16816(float* c, const uint32_t* a, const uint32_t* b) {
    asm volatile("mma.sync.aligned.m16n8k16.row.col.f32.bf16.bf16.f32 "
                 "{%0,%1,%2,%3}, {%4,%5,%6,%7}, {%8,%9}, {%0,%1,%2,%3};"
                 : "+f"(c[0]), "+f"(c[1]), "+f"(c[2]), "+f"(c[3])
                 : "r"(a[0]), "r"(a[1]), "r"(a[2]), "r"(a[3]), "r"(b[0]), "r"(b[1]));
}
__device__ __forceinline__ void split2(float x, __nv_bfloat16& h, __nv_bfloat16& l) {
    h = __float2bfloat16(x);
    l = __float2bfloat16(x - __bfloat162float(h));
}
__device__ __forceinline__ void packsplit(float a, float b, uint32_t& hh, uint32_t& ll) {
    __nv_bfloat16 h0, l0, h1, l1;
    split2(a, h0, l0);
    split2(b, h1, l1);
    __nv_bfloat162 H = __halves2bfloat162(h0, h1), L = __halves2bfloat162(l0, l1);
    hh = *(uint32_t*)&H;
    ll = *(uint32_t*)&L;
}

// =============================================================================
// K0: elementwise fp32 -> split bf16 hi/lo; grid.y selects one of 3 inputs.
// =============================================================================
__global__ void __launch_bounds__(256)
split3_kernel(const float* __restrict__ X0, const float* __restrict__ X1,
              const float* __restrict__ X2, __nv_bfloat16* __restrict__ H,
              __nv_bfloat16* __restrict__ L, size_t span)
{
    const float* X = (blockIdx.y == 0) ? X0 : (blockIdx.y == 1) ? X1 : X2;
    size_t base = (size_t)blockIdx.y * span;
    size_t i = ((size_t)blockIdx.x * 256 + threadIdx.x) * 4;
    float4 v = *(const float4*)(X + i);
    __nv_bfloat16 h[4], l[4];
    split2(v.x, h[0], l[0]); split2(v.y, h[1], l[1]);
    split2(v.z, h[2], l[2]); split2(v.w, h[3], l[3]);
    *(__nv_bfloat162*)(H + base + i)     = __halves2bfloat162(h[0], h[1]);
    *(__nv_bfloat162*)(H + base + i + 2) = __halves2bfloat162(h[2], h[3]);
    *(__nv_bfloat162*)(L + base + i)     = __halves2bfloat162(l[0], l[1]);
    *(__nv_bfloat162*)(L + base + i + 2) = __halves2bfloat162(l[2], l[3]);
}

// =============================================================================
// K1: projection  Y[m,n] = sum_k X[m,k] * W[n,k]  (z = q/k/v)
//     cp.async 2-stage pipeline, 80KB dyn smem, SINGLE sync per k-iter
//     (wait<0> -> sync -> issue next-stage load -> mma; fused_out-proven order)
// =============================================================================
__global__ void __launch_bounds__(256)
proj_mma(const __nv_bfloat16* __restrict__ Xh, const __nv_bfloat16* __restrict__ Xl,
         const __nv_bfloat16* __restrict__ Wh, const __nv_bfloat16* __restrict__ Wl,
         __nv_bfloat16* __restrict__ Yh, __nv_bfloat16* __restrict__ Yl)
{
    extern __shared__ __align__(16) __nv_bfloat16 smem[];

    const int tid = threadIdx.x, lane = tid & 31, w = tid >> 5;
    const int wm = w >> 2, wn = w & 3;
    const int z = blockIdx.z;
    const size_t xoff = (size_t)z * XN, woff = (size_t)z * WN;
    Xh += xoff; Xl += xoff; Yh += xoff; Yl += xoff; Wh += woff; Wl += woff;
    const int m0 = blockIdx.y * 128, n0 = blockIdx.x * 128;

    const int lr = tid >> 2, lc = (tid & 3) * 8;

    float acc[4][4][4] = {};

#define STG(s, off) (smem + (s) * 20480 + (off))
    auto load_stage = [&](int s, int k0) {
#pragma unroll
        for (int q = 0; q < 2; q++) {
            int r = lr + q * 64;
            cpa16(saddr_of(STG(s, 0)     + r * 40 + lc), Xh + (size_t)(m0 + r) * 1024 + k0 + lc);
            cpa16(saddr_of(STG(s, 5120)  + r * 40 + lc), Xl + (size_t)(m0 + r) * 1024 + k0 + lc);
            cpa16(saddr_of(STG(s, 10240) + r * 40 + lc), Wh + (size_t)(n0 + r) * 1024 + k0 + lc);
            cpa16(saddr_of(STG(s, 15360) + r * 40 + lc), Wl + (size_t)(n0 + r) * 1024 + k0 + lc);
        }
        cpa_commit();
    };

    load_stage(0, 0);

    for (int it = 0; it < 32; it++) {
        const int cur = it & 1;
        cpa_wait<0>();          // exactly one group outstanding: stage cur
        __syncthreads();        // also orders prior reads of cur^1 before refill
        if (it + 1 < 32) load_stage(cur ^ 1, (it + 1) * 32);

        const __nv_bfloat16* Ah = STG(cur, 0);
        const __nv_bfloat16* Al = STG(cur, 5120);
        const __nv_bfloat16* Bh = STG(cur, 10240);
        const __nv_bfloat16* Bl = STG(cur, 15360);

#pragma unroll
        for (int ks = 0; ks < 32; ks += 16) {
            uint32_t ah[4][4], al[4][4], bh[4][2], bl[4][2];
#pragma unroll
            for (int mt = 0; mt < 4; mt++) {
                int row = wm * 64 + mt * 16 + (lane & 15);
                int col = ks + ((lane >> 4) << 3);
                ldsm4(ah[mt], saddr_of(Ah + row * 40 + col));
                ldsm4(al[mt], saddr_of(Al + row * 40 + col));
            }
#pragma unroll
            for (int p = 0; p < 2; p++) {
                int row = wn * 32 + p * 16 + ((lane >> 4) << 3) + (lane & 7);
                int col = ks + (((lane >> 3) & 1) << 3);
                uint32_t t4[4];
                ldsm4(t4, saddr_of(Bh + row * 40 + col));
                bh[p * 2][0] = t4[0]; bh[p * 2][1] = t4[1];
                bh[p * 2 + 1][0] = t4[2]; bh[p * 2 + 1][1] = t4[3];
                ldsm4(t4, saddr_of(Bl + row * 40 + col));
                bl[p * 2][0] = t4[0]; bl[p * 2][1] = t4[1];
                bl[p * 2 + 1][0] = t4[2]; bl[p * 2 + 1][1] = t4[3];
            }
#pragma unroll
            for (int mt = 0; mt < 4; mt++)
#pragma unroll
                for (int nt = 0; nt < 4; nt++) {
                    mma16816(acc[mt][nt], ah[mt], bh[nt]);
                    mma16816(acc[mt][nt], ah[mt], bl[nt]);
                    mma16816(acc[mt][nt], al[mt], bh[nt]);
                }
        }
    }
#undef STG

    const int gr = lane >> 2, gc = (lane & 3) << 1;
#pragma unroll
    for (int mt = 0; mt < 4; mt++)
#pragma unroll
        for (int nt = 0; nt < 4; nt++) {
            int m = m0 + wm * 64 + mt * 16 + gr;
            int n = n0 + wn * 32 + nt * 8 + gc;
#pragma unroll
            for (int hf = 0; hf < 2; hf++) {
                float c0 = acc[mt][nt][hf * 2], c1 = acc[mt][nt][hf * 2 + 1];
                __nv_bfloat16 h0, l0, h1, l1;
                split2(c0, h0, l0);
                split2(c1, h1, l1);
                size_t off = (size_t)(m + hf * 8) * 1024 + n;
                *(__nv_bfloat162*)(Yh + off) = __halves2bfloat162(h0, h1);
                *(__nv_bfloat162*)(Yl + off) = __halves2bfloat162(l0, l1);
            }
        }
}

// =============================================================================
// K2: zscore — S = QK^T, exp, deterministic row-sum partials ONLY (no E write).
// =============================================================================
__global__ void __launch_bounds__(256)
zscore_mma(const __nv_bfloat16* __restrict__ Qh, const __nv_bfloat16* __restrict__ Ql,
           const __nv_bfloat16* __restrict__ Kh, const __nv_bfloat16* __restrict__ Kl,
           float* __restrict__ Zp)
{
    extern __shared__ __align__(16) __nv_bfloat16 smem[];
    __nv_bfloat16* Ah = smem;            // [128][72]
    __nv_bfloat16* Al = smem + 9216;
    __nv_bfloat16* Bh = smem + 18432;
    __nv_bfloat16* Bl = smem + 27648;
    __shared__ __align__(16) float srow[128][4];

    const int tid = threadIdx.x, lane = tid & 31, w = tid >> 5;
    const int wm = w >> 2, wn = w & 3;
    const int bhz = blockIdx.z, b = bhz >> 4, h = bhz & 15;
    const int m0 = blockIdx.y * 128, n0 = blockIdx.x * 128;

    const size_t qbase = (size_t)(b * 1024 + m0) * 1024 + h * 64;
    const size_t kbase = (size_t)(b * 1024 + n0) * 1024 + h * 64;

#pragma unroll
    for (int it = 0; it < 4; it++) {
        int id = tid + it * 256;
        int r = id >> 3, c = (id & 7) * 8;
        cpa16(saddr_of(Ah + r * 72 + c), Qh + qbase + (size_t)r * 1024 + c);
        cpa16(saddr_of(Al + r * 72 + c), Ql + qbase + (size_t)r * 1024 + c);
        cpa16(saddr_of(Bh + r * 72 + c), Kh + kbase + (size_t)r * 1024 + c);
        cpa16(saddr_of(Bl + r * 72 + c), Kl + kbase + (size_t)r * 1024 + c);
    }
    cpa_commit();
    cpa_wait<0>();
    __syncthreads();

    float acc[4][4][4] = {};
#pragma unroll
    for (int ks = 0; ks < 64; ks += 16) {
        uint32_t ah[4][4], al[4][4], bh[4][2], bl[4][2];
#pragma unroll
        for (int mt = 0; mt < 4; mt++) {
            int row = wm * 64 + mt * 16 + (lane & 15);
            int col = ks + ((lane >> 4) << 3);
            ldsm4(ah[mt], saddr_of(Ah + row * 72 + col));
            ldsm4(al[mt], saddr_of(Al + row * 72 + col));
        }
#pragma unroll
        for (int p = 0; p < 2; p++) {
            int row = wn * 32 + p * 16 + ((lane >> 4) << 3) + (lane & 7);
            int col = ks + (((lane >> 3) & 1) << 3);
            uint32_t t4[4];
            ldsm4(t4, saddr_of(Bh + row * 72 + col));
            bh[p * 2][0] = t4[0]; bh[p * 2][1] = t4[1];
            bh[p * 2 + 1][0] = t4[2]; bh[p * 2 + 1][1] = t4[3];
            ldsm4(t4, saddr_of(Bl + row * 72 + col));
            bl[p * 2][0] = t4[0]; bl[p * 2][1] = t4[1];
            bl[p * 2 + 1][0] = t4[2]; bl[p * 2 + 1][1] = t4[3];
        }
#pragma unroll
        for (int mt = 0; mt < 4; mt++)
#pragma unroll
            for (int nt = 0; nt < 4; nt++) {
                mma16816(acc[mt][nt], ah[mt], bh[nt]);
                mma16816(acc[mt][nt], ah[mt], bl[nt]);
                mma16816(acc[mt][nt], al[mt], bh[nt]);
            }
    }

#pragma unroll
    for (int mt = 0; mt < 4; mt++)
#pragma unroll
        for (int nt = 0; nt < 4; nt++)
#pragma unroll
            for (int q = 0; q < 4; q++)
                acc[mt][nt][q] = __expf(acc[mt][nt][q] * 0.125f);

    const int gr = lane >> 2;

#pragma unroll
    for (int mt = 0; mt < 4; mt++) {
        float s_lo = 0.f, s_hi = 0.f;
#pragma unroll
        for (int nt = 0; nt < 4; nt++) {
            s_lo += acc[mt][nt][0] + acc[mt][nt][1];
            s_hi += acc[mt][nt][2] + acc[mt][nt][3];
        }
        s_lo += __shfl_xor_sync(0xffffffffu, s_lo, 1);
        s_lo += __shfl_xor_sync(0xffffffffu, s_lo, 2);
        s_hi += __shfl_xor_sync(0xffffffffu, s_hi, 1);
        s_hi += __shfl_xor_sync(0xffffffffu, s_hi, 2);
        if ((lane & 3) == 0) {
            srow[wm * 64 + mt * 16 + gr][wn]     = s_lo;
            srow[wm * 64 + mt * 16 + gr + 8][wn] = s_hi;
        }
    }
    __syncthreads();
    if (tid < 128) {
        float zp = srow[tid][0] + srow[tid][1] + srow[tid][2] + srow[tid][3];
        Zp[((size_t)(bhz << 10) + m0 + tid) * 8 + (n0 >> 7)] = zp;
    }
}

// =============================================================================
// K3: fused zred+vscale. One warp per (bh,j) row.
// =============================================================================
__global__ void __launch_bounds__(256)
zvscale_kernel(const __nv_bfloat16* __restrict__ Vh, const __nv_bfloat16* __restrict__ Vl,
               const float* __restrict__ Zp,
               __nv_bfloat16* __restrict__ Ph, __nv_bfloat16* __restrict__ Pl)
{
    int wid = blockIdx.x * 8 + (threadIdx.x >> 5);   // 0 .. 131071 (bh*1024 + j)
    int lane = threadIdx.x & 31;
    int bh = wid >> 10, j = wid & 1023;
    int b = bh >> 4, h = bh & 15;

    float zpart = (lane < 8) ? Zp[(size_t)wid * 8 + lane] : 0.f;
    zpart += __shfl_xor_sync(0xffffffffu, zpart, 4);
    zpart += __shfl_xor_sync(0xffffffffu, zpart, 2);
    zpart += __shfl_xor_sync(0xffffffffu, zpart, 1);
    float inv = 1.f / __shfl_sync(0xffffffffu, zpart, 0);

    size_t src = (size_t)(b * 1024 + j) * 1024 + h * 64 + lane * 2;
    __nv_bfloat162 vh2 = *(const __nv_bfloat162*)(Vh + src);
    __nv_bfloat162 vl2 = *(const __nv_bfloat162*)(Vl + src);
    float v0 = (__bfloat162float(__low2bfloat16(vh2)) + __bfloat162float(__low2bfloat16(vl2))) * inv;
    float v1 = (__bfloat162float(__high2bfloat16(vh2)) + __bfloat162float(__high2bfloat16(vl2))) * inv;
    __nv_bfloat16 h0, l0, h1, l1;
    split2(v0, h0, l0);
    split2(v1, h1, l1);
    size_t dst = (size_t)wid * 64 + lane * 2;
    *(__nv_bfloat162*)(Ph + dst) = __halves2bfloat162(h0, h1);
    *(__nv_bfloat162*)(Pl + dst) = __halves2bfloat162(l0, l1);
}

// =============================================================================
// K4: fused out, j-chunk = 32, 2 CTAs/SM (regs capped at 128; K frags
//     reloaded per chunk from resident smem tile instead of hoisted).
//     out[i,d] = sum_{j<=i} exp(s[j,i]) * V'[j,d].
// =============================================================================
__global__ void __launch_bounds__(256, 2)
fused_out(const __nv_bfloat16* __restrict__ Qh, const __nv_bfloat16* __restrict__ Ql,
          const __nv_bfloat16* __restrict__ Kh, const __nv_bfloat16* __restrict__ Kl,
          const __nv_bfloat16* __restrict__ Vh, const __nv_bfloat16* __restrict__ Vl,
          float* __restrict__ Out)
{
    extern __shared__ __align__(16) __nv_bfloat16 smem[];
    __nv_bfloat16* Ksh = smem;
    __nv_bfloat16* Ksl = smem + 9216;

    const int tid = threadIdx.x, lane = tid & 31, w = tid >> 5;
    const int bhz = blockIdx.y, b = bhz >> 4, h = bhz & 15;
    const int i0 = (7 - (int)blockIdx.x) * 128;   // longest-first

    const size_t kbase = (size_t)(b * 1024 + i0) * 1024 + h * 64;
    const size_t qrow0 = (size_t)(b * 1024) * 1024 + h * 64;
    const size_t vrow0 = (size_t)bhz << 16;       // V' compact [bh*1024 + j][64]

    const int gr = lane >> 2, gc = (lane & 3) << 1;
    const int njc = (i0 >> 5) + 4;

#pragma unroll
    for (int it = 0; it < 4; it++) {
        int id = tid + it * 256;
        int r = id >> 3, c = (id & 7) * 8;
        cpa16(saddr_of(Ksh + r * 72 + c), Kh + kbase + (size_t)r * 1024 + c);
        cpa16(saddr_of(Ksl + r * 72 + c), Kl + kbase + (size_t)r * 1024 + c);
    }

    auto load_chunk = [&](int jc, int s) {
        __nv_bfloat16* Qsh = smem + 18432 + s * 4608;
        __nv_bfloat16* Qsl = Qsh + 2304;
        __nv_bfloat16* Vsh = smem + 27648 + s * 4608;
        __nv_bfloat16* Vsl = Vsh + 2304;
        int r = tid >> 3, c = (tid & 7) * 8;
        int j0 = jc * 32;
        cpa16(saddr_of(Qsh + r * 72 + c), Qh + qrow0 + (size_t)(j0 + r) * 1024 + c);
        cpa16(saddr_of(Qsl + r * 72 + c), Ql + qrow0 + (size_t)(j0 + r) * 1024 + c);
        cpa16(saddr_of(Vsh + r * 72 + c), Vh + vrow0 + (size_t)(j0 + r) * 64 + c);
        cpa16(saddr_of(Vsl + r * 72 + c), Vl + vrow0 + (size_t)(j0 + r) * 64 + c);
        cpa_commit();
    };

    load_chunk(0, 0);
    cpa_wait<0>();
    __syncthreads();

    if (njc > 1) load_chunk(1, 1);

    float acc2[8][4] = {};
    const int ibase = i0 + w * 16 + gr;

    for (int jc = 0; jc < njc; jc++) {
        const int s = jc & 1;
        cpa_wait<0>();
        __syncthreads();
        if (jc + 1 < njc) load_chunk(jc + 1, s ^ 1);

        const __nv_bfloat16* Qsh = smem + 18432 + s * 4608;
        const __nv_bfloat16* Qsl = Qsh + 2304;
        const __nv_bfloat16* Vsh = smem + 27648 + s * 4608;
        const __nv_bfloat16* Vsl = Vsh + 2304;

        float acc1[4][4] = {};
#pragma unroll
        for (int kd = 0; kd < 4; kd++) {
            int ks = kd * 16;
            uint32_t kah[4], kal[4];
            {
                int row = w * 16 + (lane & 15);
                int col = ks + ((lane >> 4) << 3);
                ldsm4(kah, saddr_of(Ksh + row * 72 + col));
                ldsm4(kal, saddr_of(Ksl + row * 72 + col));
            }
            uint32_t qbh[4][2], qbl[4][2];
#pragma unroll
            for (int p = 0; p < 2; p++) {
                int row = p * 16 + ((lane >> 4) << 3) + (lane & 7);
                int col = ks + (((lane >> 3) & 1) << 3);
                uint32_t t4[4];
                ldsm4(t4, saddr_of(Qsh + row * 72 + col));
                qbh[p * 2][0] = t4[0]; qbh[p * 2][1] = t4[1];
                qbh[p * 2 + 1][0] = t4[2]; qbh[p * 2 + 1][1] = t4[3];
                ldsm4(t4, saddr_of(Qsl + row * 72 + col));
                qbl[p * 2][0] = t4[0]; qbl[p * 2][1] = t4[1];
                qbl[p * 2 + 1][0] = t4[2]; qbl[p * 2 + 1][1] = t4[3];
            }
#pragma unroll
            for (int nt = 0; nt < 4; nt++) {
                mma16816(acc1[nt], kah, qbh[nt]);
                mma16816(acc1[nt], kah, qbl[nt]);
                mma16816(acc1[nt], kal, qbh[nt]);
            }
        }

        const int j0 = jc * 32;
#pragma unroll
        for (int nt = 0; nt < 4; nt++) {
            int jg = j0 + nt * 8 + gc;
#pragma unroll
            for (int q = 0; q < 4; q++) {
                int jj = jg + (q & 1);
                int ii = ibase + ((q >> 1) << 3);
                acc1[nt][q] = (jj <= ii) ? __expf(acc1[nt][q] * 0.125f) : 0.f;
            }
        }

        uint32_t pah[2][4], pal[2][4];
#pragma unroll
        for (int kj = 0; kj < 2; kj++) {
            const float* x0 = acc1[2 * kj];
            const float* x1 = acc1[2 * kj + 1];
            packsplit(x0[0], x0[1], pah[kj][0], pal[kj][0]);
            packsplit(x0[2], x0[3], pah[kj][1], pal[kj][1]);
            packsplit(x1[0], x1[1], pah[kj][2], pal[kj][2]);
            packsplit(x1[2], x1[3], pah[kj][3], pal[kj][3]);
        }

#pragma unroll
        for (int kj = 0; kj < 2; kj++) {
            int kr = kj * 16 + (((lane >> 3) & 1) << 3) + (lane & 7);
            uint32_t vbh[8][2], vbl[8][2];
#pragma unroll
            for (int qd = 0; qd < 4; qd++) {
                int dc = qd * 16 + ((lane >> 4) << 3);
                uint32_t t4[4];
                ldsm4t(t4, saddr_of(Vsh + kr * 72 + dc));
                vbh[qd * 2][0] = t4[0]; vbh[qd * 2][1] = t4[1];
                vbh[qd * 2 + 1][0] = t4[2]; vbh[qd * 2 + 1][1] = t4[3];
                ldsm4t(t4, saddr_of(Vsl + kr * 72 + dc));
                vbl[qd * 2][0] = t4[0]; vbl[qd * 2][1] = t4[1];
                vbl[qd * 2 + 1][0] = t4[2]; vbl[qd * 2 + 1][1] = t4[3];
            }
#pragma unroll
            for (int nt2 = 0; nt2 < 8; nt2++) {
                mma16816(acc2[nt2], pah[kj], vbh[nt2]);
                mma16816(acc2[nt2], pah[kj], vbl[nt2]);
                mma16816(acc2[nt2], pal[kj], vbh[nt2]);
            }
        }
        __syncthreads();
    }

#pragma unroll
    for (int nt2 = 0; nt2 < 8; nt2++) {
        int d = nt2 * 8 + gc;
#pragma unroll
        for (int hf = 0; hf < 2; hf++) {
            int i = ibase + hf * 8;
            *(float2*)(Out + (size_t)(b * 1024 + i) * 1024 + h * 64 + d) =
                make_float2(acc2[nt2][hf * 2], acc2[nt2][hf * 2 + 1]);
        }
    }
}

// =============================================================================
extern "C" void kernel_launch(void* const* d_in, const int* in_sizes, int n_in,
                              void* d_out, int out_size)
{
    const float* q  = (const float*)d_in[0];
    const float* k  = (const float*)d_in[1];
    const float* v  = (const float*)d_in[2];
    const float* Wq = (const float*)d_in[3];
    const float* Wk = (const float*)d_in[4];
    const float* Wv = (const float*)d_in[5];
    float* out = (float*)d_out;
    (void)in_sizes; (void)n_in; (void)out_size;

    __nv_bfloat16 *xh, *xl, *wh, *wl, *yh, *yl, *vph, *vpl;
    float *zp;
    cudaGetSymbolAddress((void**)&xh, g_xh);
    cudaGetSymbolAddress((void**)&xl, g_xl);
    cudaGetSymbolAddress((void**)&wh, g_wh);
    cudaGetSymbolAddress((void**)&wl, g_wl);
    cudaGetSymbolAddress((void**)&yh, g_yh);
    cudaGetSymbolAddress((void**)&yl, g_yl);
    cudaGetSymbolAddress((void**)&zp, g_zp);
    cudaGetSymbolAddress((void**)&vph, g_vph);
    cudaGetSymbolAddress((void**)&vpl, g_vpl);

    cudaFuncSetAttribute(proj_mma,   cudaFuncAttributeMaxDynamicSharedMemorySize, 81920);
    cudaFuncSetAttribute(zscore_mma, cudaFuncAttributeMaxDynamicSharedMemorySize, 73728);
    cudaFuncSetAttribute(fused_out,  cudaFuncAttributeMaxDynamicSharedMemorySize, 73728);

    split3_kernel<<<dim3(XN / 1024, 3), 256>>>(q, k, v, xh, xl, (size_t)XN);
    split3_kernel<<<dim3(WN / 1024, 3), 256>>>(Wq, Wk, Wv, wh, wl, (size_t)WN);

    proj_mma<<<dim3(8, 64, 3), 256, 81920>>>(xh, xl, wh, wl, yh, yl);

    dim3 sgrid(8, 8, BATCH * NHEADS);
    zscore_mma<<<sgrid, 256, 73728>>>(yh, yl, yh + XN, yl + XN, zp);

    zvscale_kernel<<<16384, 256>>>(yh + 2 * XN, yl + 2 * XN, zp, vph, vpl);

    fused_out<<<dim3(8, BATCH * NHEADS), 256, 73728>>>(
        yh, yl, yh + XN, yl + XN, vph, vpl, out);
}